// round 3
// baseline (speedup 1.0000x reference)
#include <cuda_runtime.h>

// ---------------------------------------------------------------------------
// SRNN text encoder, restructured:
//   1) X[b][t][4H] = emb[x[b,t]] @ Wih^T + (bih+bhh)    (both directions)
//   2) fwd chains (one per start p), bwd chains (one per end q), advanced in
//      32 fused step kernels; running cumsum of h stored per (chain, t).
//   3) per-span mean vector = cumsum lookup / (k+1)
//   4) out = Mean @ Wout^T + bout   (one big GEMM, writes d_out directly)
// ---------------------------------------------------------------------------

#define NB    8
#define NT    32
#define HD    512
#define G4    2048
#define NSPAN 496
#define MROWS 3968          // 8*496
#define NOUT  7680          // 30*256

// scratch (device globals; allocation APIs are forbidden)
__device__ float g_Xf[NB*NT*G4];
__device__ float g_Xb[NB*NT*G4];
__device__ float g_Af[NB*NT*NT*HD];   // cumsum of fwd h: [chain=b*32+p][t][u]
__device__ float g_Ab[NB*NT*NT*HD];   // cumsum of bwd h: [chain=b*32+q][t][u]
__device__ float g_Hf0[NB*NT*HD];
__device__ float g_Hf1[NB*NT*HD];
__device__ float g_Hb0[NB*NT*HD];
__device__ float g_Hb1[NB*NT*HD];
__device__ float g_Cf[NB*NT*HD];
__device__ float g_Cb[NB*NT*HD];
__device__ float g_Mean[MROWS*1024];

// ---------------------------------------------------------------------------
// Generic fp32 GEMM: C[M,N] = A[M,K] @ B[N,K]^T + bias1 (+bias2)
// A rows optionally gathered through rowidx. M,N multiples of 128, K of 8.
// mode: 0 -> C=g_Xf, A=ext(gather); 1 -> C=g_Xb, A=ext(gather); 2 -> A=g_Mean, C=ext
// ---------------------------------------------------------------------------
__global__ __launch_bounds__(256)
void gemm_kernel(const float* __restrict__ Aext, const int* __restrict__ rowidx,
                 const float* __restrict__ Bm, const float* __restrict__ bias1,
                 const float* __restrict__ bias2, float* __restrict__ Cext,
                 int M, int N, int K, int mode)
{
    const float* A = (mode == 2) ? g_Mean : Aext;
    float*       C = (mode == 2) ? Cext : (mode == 1 ? g_Xb : g_Xf);

    __shared__ float As[8][128];
    __shared__ float Bs[8][128];

    int tid = threadIdx.x;
    int tx = tid & 15, ty = tid >> 4;
    int m0 = blockIdx.y * 128, n0 = blockIdx.x * 128;

    float acc[8][8];
#pragma unroll
    for (int i = 0; i < 8; i++)
#pragma unroll
        for (int j = 0; j < 8; j++) acc[i][j] = 0.f;

    for (int k0 = 0; k0 < K; k0 += 8) {
#pragma unroll
        for (int r = 0; r < 4; r++) {
            int e = r * 256 + tid;
            int kk = e & 7, row = e >> 3;
            int ar = rowidx ? rowidx[m0 + row] : (m0 + row);
            As[kk][row] = A[(size_t)ar * K + k0 + kk];
            Bs[kk][row] = Bm[(size_t)(n0 + row) * K + k0 + kk];
        }
        __syncthreads();
#pragma unroll
        for (int kk = 0; kk < 8; kk++) {
            float4 a0 = *(const float4*)&As[kk][ty * 8];
            float4 a1 = *(const float4*)&As[kk][ty * 8 + 4];
            float4 b0 = *(const float4*)&Bs[kk][tx * 8];
            float4 b1 = *(const float4*)&Bs[kk][tx * 8 + 4];
            float av[8] = {a0.x, a0.y, a0.z, a0.w, a1.x, a1.y, a1.z, a1.w};
            float bv[8] = {b0.x, b0.y, b0.z, b0.w, b1.x, b1.y, b1.z, b1.w};
#pragma unroll
            for (int i = 0; i < 8; i++)
#pragma unroll
                for (int j = 0; j < 8; j++)
                    acc[i][j] += av[i] * bv[j];
        }
        __syncthreads();
    }

#pragma unroll
    for (int i = 0; i < 8; i++) {
        float* crow = C + (size_t)(m0 + ty * 8 + i) * N + n0 + tx * 8;
#pragma unroll
        for (int j = 0; j < 8; j++) {
            int n = n0 + tx * 8 + j;
            float v = acc[i][j] + bias1[n];
            if (bias2) v += bias2[n];
            crow[j] = v;
        }
    }
}

// ---------------------------------------------------------------------------
// One LSTM time step for all active chains, both directions.
// dir 0: time t=s, chains (b, p<=s), new chain when p==s
// dir 1: time t=31-s, chains (b, q>=31-s), new chain when q==31-s
// Block: 64-unit slice (u0=blockIdx.x*64) x 16-chain tile (blockIdx.y).
// Computes gates = X + h_prev @ Whh^T, applies cell, updates H/C and cumsum A.
// H is double-buffered across steps (read s&1, write the other).
// ---------------------------------------------------------------------------
__global__ __launch_bounds__(256)
void lstm_step_kernel(const float* __restrict__ Whh_f,
                      const float* __restrict__ Whh_b, int s)
{
    int dir = blockIdx.z;
    int t = dir ? (31 - s) : s;
    int L = s + 1;
    int M = 8 * L;
    int ct = blockIdx.y;
    int u0 = blockIdx.x * 64;
    int tid = threadIdx.x;
    int u = tid & 63;
    int mg = tid >> 6;

    const float* Whh = dir ? Whh_b : Whh_f;
    const float* Xd  = dir ? g_Xb  : g_Xf;
    float* Hrd = dir ? ((s & 1) ? g_Hb1 : g_Hb0) : ((s & 1) ? g_Hf1 : g_Hf0);
    float* Hwr = dir ? ((s & 1) ? g_Hb0 : g_Hb1) : ((s & 1) ? g_Hf0 : g_Hf1);
    float* Cst = dir ? g_Cb : g_Cf;
    float* Ad  = dir ? g_Ab : g_Af;

    __shared__ float ws[256][33];
    __shared__ float hs[16][32];

    float acc[4][4];
#pragma unroll
    for (int g = 0; g < 4; g++)
#pragma unroll
        for (int i = 0; i < 4; i++) acc[g][i] = 0.f;

    for (int k0 = 0; k0 < 512; k0 += 32) {
#pragma unroll
        for (int r = 0; r < 32; r++) {
            int e = r * 256 + tid;
            int kk = e & 31, row = e >> 5;          // row = gate*64 + unit
            ws[row][kk] = Whh[(size_t)((row >> 6) * 512 + u0 + (row & 63)) * 512 + k0 + kk];
        }
#pragma unroll
        for (int r = 0; r < 2; r++) {
            int e = r * 256 + tid;
            int kk = e & 31, m = e >> 5;            // m = chain within tile
            int cl = ct * 16 + m;
            float v = 0.f;
            if (cl < M) {
                int bb = cl / L, jj = cl - bb * L;
                int pos = dir ? (t + jj) : jj;
                bool nw = dir ? (jj == 0) : (jj == s);
                if (!nw) v = Hrd[(bb * 32 + pos) * 512 + k0 + kk];
            }
            hs[m][kk] = v;
        }
        __syncthreads();
#pragma unroll
        for (int kk = 0; kk < 32; kk++) {
            float h0 = hs[mg * 4 + 0][kk];
            float h1 = hs[mg * 4 + 1][kk];
            float h2 = hs[mg * 4 + 2][kk];
            float h3 = hs[mg * 4 + 3][kk];
            float w0 = ws[u][kk];
            float w1 = ws[64 + u][kk];
            float w2 = ws[128 + u][kk];
            float w3 = ws[192 + u][kk];
            acc[0][0] += w0 * h0; acc[0][1] += w0 * h1; acc[0][2] += w0 * h2; acc[0][3] += w0 * h3;
            acc[1][0] += w1 * h0; acc[1][1] += w1 * h1; acc[1][2] += w1 * h2; acc[1][3] += w1 * h3;
            acc[2][0] += w2 * h0; acc[2][1] += w2 * h1; acc[2][2] += w2 * h2; acc[2][3] += w2 * h3;
            acc[3][0] += w3 * h0; acc[3][1] += w3 * h1; acc[3][2] += w3 * h2; acc[3][3] += w3 * h3;
        }
        __syncthreads();
    }

    int ug = u0 + u;
#pragma unroll
    for (int i = 0; i < 4; i++) {
        int cl = ct * 16 + mg * 4 + i;
        if (cl >= M) continue;
        int bb = cl / L, jj = cl - bb * L;
        int pos = dir ? (t + jj) : jj;
        bool nw = dir ? (jj == 0) : (jj == s);
        int chain = bb * 32 + pos;
        const float* Xrow = Xd + (size_t)(bb * 32 + t) * 2048;
        float gi = acc[0][i] + Xrow[ug];
        float gf = acc[1][i] + Xrow[512 + ug];
        float gg = acc[2][i] + Xrow[1024 + ug];
        float go = acc[3][i] + Xrow[1536 + ug];
        float cprev = nw ? 0.f : Cst[chain * 512 + ug];
        float ig = 1.f / (1.f + __expf(-gi));
        float fg = 1.f / (1.f + __expf(-gf));
        float og = 1.f / (1.f + __expf(-go));
        float gt = tanhf(gg);
        float cc = fg * cprev + ig * gt;
        float hh = og * tanhf(cc);
        Cst[chain * 512 + ug] = cc;
        Hwr[chain * 512 + ug] = hh;
        int tprev = dir ? (t + 1) : (t - 1);
        float aprev = nw ? 0.f : Ad[((size_t)chain * 32 + tprev) * 512 + ug];
        Ad[((size_t)chain * 32 + t) * 512 + ug] = aprev + hh;
    }
}

// ---------------------------------------------------------------------------
// Build per-span mean vectors: Mean[b*496+sidx][0:512]  = Af[b,p][q]/(k+1)
//                              Mean[...][512:1024]      = Ab[b,q][p]/(k+1)
// ---------------------------------------------------------------------------
__global__ __launch_bounds__(256)
void mean_kernel()
{
    int sidx = blockIdx.x;          // 0..495 (ordered by k then start p)
    int b = blockIdx.y;
    int k = 1, off = 0;
    while (off + (32 - k) <= sidx) { off += (32 - k); k++; }
    int p = sidx - off;
    int q = p + k;
    float inv = 1.f / (float)(k + 1);

    int tid = threadIdx.x;
    float* dst = g_Mean + (size_t)(b * 496 + sidx) * 1024;
    const float* af = g_Af + (((size_t)(b * 32 + p)) * 32 + q) * 512;
    const float* ab = g_Ab + (((size_t)(b * 32 + q)) * 32 + p) * 512;
    for (int uu = tid; uu < 512; uu += 256) {
        dst[uu]       = af[uu] * inv;
        dst[512 + uu] = ab[uu] * inv;
    }
}

// ---------------------------------------------------------------------------
extern "C" void kernel_launch(void* const* d_in, const int* in_sizes, int n_in,
                              void* d_out, int out_size)
{
    const int*   x     = (const int*)  d_in[0];
    // d_in[1] = lengths (always N, unused by the reference math)
    const float* emb   = (const float*)d_in[2];
    const float* Wih_f = (const float*)d_in[3];
    const float* Whh_f = (const float*)d_in[4];
    const float* bih_f = (const float*)d_in[5];
    const float* bhh_f = (const float*)d_in[6];
    const float* Wih_b = (const float*)d_in[7];
    const float* Whh_b = (const float*)d_in[8];
    const float* bih_b = (const float*)d_in[9];
    const float* bhh_b = (const float*)d_in[10];
    const float* Wout  = (const float*)d_in[11];
    const float* bout  = (const float*)d_in[12];
    float* out = (float*)d_out;

    dim3 blk(256);

    // 1) input-gate precompute (gathered GEMM): [256,512] @ [512,2048]^T
    gemm_kernel<<<dim3(16, 2), blk>>>(emb, x, Wih_f, bih_f, bhh_f, nullptr,
                                      256, 2048, 512, 0);
    gemm_kernel<<<dim3(16, 2), blk>>>(emb, x, Wih_b, bih_b, bhh_b, nullptr,
                                      256, 2048, 512, 1);

    // 2) 32 recurrence steps (fwd + bwd fused per step)
    for (int s = 0; s < 32; s++) {
        int ctiles = (8 * (s + 1) + 15) / 16;
        lstm_step_kernel<<<dim3(8, ctiles, 2), blk>>>(Whh_f, Whh_b, s);
    }

    // 3) span means
    mean_kernel<<<dim3(496, 8), blk>>>();

    // 4) projection GEMM: [3968,1024] @ [1024,7680]^T -> d_out
    gemm_kernel<<<dim3(60, 31), blk>>>(nullptr, nullptr, Wout, bout, nullptr,
                                       out, 3968, 7680, 1024, 2);
}

// round 4
// speedup vs baseline: 1.0463x; 1.0463x over previous
#include <cuda_runtime.h>

// ---------------------------------------------------------------------------
// SRNN text encoder:
//   1) X[b][t][4H] = emb[x[b,t]] @ Wih^T + (bih+bhh)     (both directions)
//   2) persistent recurrence kernel: weights resident in smem, 32 steps with
//      a grid barrier between steps; running cumsum of h stored per (chain,t)
//   3) per-span mean vector = cumsum lookup / (k+1)
//   4) out = Mean @ Wout^T + bout   (one GEMM, packed f32x2 FMA)
// ---------------------------------------------------------------------------

#define NB    8
#define NT    32
#define HD    512
#define G4    2048
#define MROWS 3968          // 8*496
#define NOUT  7680          // 30*256

typedef unsigned long long ull;

// scratch (device globals; allocation APIs are forbidden)
__device__ float g_Xf[NB*NT*G4];
__device__ float g_Xb[NB*NT*G4];
__device__ float g_Af[NB*NT*NT*HD];   // cumsum fwd h: [chain=b*32+p][t][u]
__device__ float g_Ab[NB*NT*NT*HD];   // cumsum bwd h: [chain=b*32+q][t][u]
__device__ float g_Hf0[NB*NT*HD];
__device__ float g_Hf1[NB*NT*HD];
__device__ float g_Hb0[NB*NT*HD];
__device__ float g_Hb1[NB*NT*HD];
__device__ float g_Cf[NB*NT*HD];
__device__ float g_Cb[NB*NT*HD];
__device__ float g_Mean[MROWS*1024];
__device__ unsigned g_barrier[32];

// ---- packed fp32 helpers (FFMA2) ------------------------------------------
__device__ __forceinline__ void ffma2(ull &acc, ull a, ull b) {
    asm("fma.rn.f32x2 %0, %1, %2, %0;" : "+l"(acc) : "l"(a), "l"(b));
}
__device__ __forceinline__ ull pack2(float x, float y) {
    ull r; asm("mov.b64 %0, {%1, %2};" : "=l"(r) : "f"(x), "f"(y)); return r;
}
__device__ __forceinline__ float2 unpk(ull v) {
    float2 r; asm("mov.b64 {%0, %1}, %2;" : "=f"(r.x), "=f"(r.y) : "l"(v)); return r;
}

// ---------------------------------------------------------------------------
// zero the grid-barrier counters (fresh every replay)
// ---------------------------------------------------------------------------
__global__ void zero_bar_kernel() {
    if (threadIdx.x < 32) g_barrier[threadIdx.x] = 0;
}

// ---------------------------------------------------------------------------
// Generic fp32 GEMM (f32x2 inner): C[M,N] = A[M,K] @ B[N,K]^T + bias1 (+bias2)
// mode: 0 -> C=g_Xf, A=ext(gather); 1 -> C=g_Xb, A=ext(gather); 2 -> A=g_Mean
// ---------------------------------------------------------------------------
__global__ __launch_bounds__(256)
void gemm_kernel(const float* __restrict__ Aext, const int* __restrict__ rowidx,
                 const float* __restrict__ Bm, const float* __restrict__ bias1,
                 const float* __restrict__ bias2, float* __restrict__ Cext,
                 int M, int N, int K, int mode)
{
    const float* A = (mode == 2) ? g_Mean : Aext;
    float*       C = (mode == 2) ? Cext : (mode == 1 ? g_Xb : g_Xf);

    __shared__ float As[8][128];
    __shared__ float Bs[8][128];

    int tid = threadIdx.x;
    int tx = tid & 15, ty = tid >> 4;
    int m0 = blockIdx.y * 128, n0 = blockIdx.x * 128;

    ull acc[8][4];
#pragma unroll
    for (int i = 0; i < 8; i++)
#pragma unroll
        for (int j = 0; j < 4; j++) acc[i][j] = 0ull;   // bits of (0.f,0.f)

    for (int k0 = 0; k0 < K; k0 += 8) {
#pragma unroll
        for (int r = 0; r < 4; r++) {
            int e = r * 256 + tid;
            int kk = e & 7, row = e >> 3;
            int ar = rowidx ? rowidx[m0 + row] : (m0 + row);
            As[kk][row] = A[(size_t)ar * K + k0 + kk];
            Bs[kk][row] = Bm[(size_t)(n0 + row) * K + k0 + kk];
        }
        __syncthreads();
#pragma unroll
        for (int kk = 0; kk < 8; kk++) {
            float4 a0 = *(const float4*)&As[kk][ty * 8];
            float4 a1 = *(const float4*)&As[kk][ty * 8 + 4];
            ulonglong2 b0 = *(const ulonglong2*)&Bs[kk][tx * 8];
            ulonglong2 b1 = *(const ulonglong2*)&Bs[kk][tx * 8 + 4];
            ull ad;
            ad = pack2(a0.x, a0.x);
            ffma2(acc[0][0], ad, b0.x); ffma2(acc[0][1], ad, b0.y);
            ffma2(acc[0][2], ad, b1.x); ffma2(acc[0][3], ad, b1.y);
            ad = pack2(a0.y, a0.y);
            ffma2(acc[1][0], ad, b0.x); ffma2(acc[1][1], ad, b0.y);
            ffma2(acc[1][2], ad, b1.x); ffma2(acc[1][3], ad, b1.y);
            ad = pack2(a0.z, a0.z);
            ffma2(acc[2][0], ad, b0.x); ffma2(acc[2][1], ad, b0.y);
            ffma2(acc[2][2], ad, b1.x); ffma2(acc[2][3], ad, b1.y);
            ad = pack2(a0.w, a0.w);
            ffma2(acc[3][0], ad, b0.x); ffma2(acc[3][1], ad, b0.y);
            ffma2(acc[3][2], ad, b1.x); ffma2(acc[3][3], ad, b1.y);
            ad = pack2(a1.x, a1.x);
            ffma2(acc[4][0], ad, b0.x); ffma2(acc[4][1], ad, b0.y);
            ffma2(acc[4][2], ad, b1.x); ffma2(acc[4][3], ad, b1.y);
            ad = pack2(a1.y, a1.y);
            ffma2(acc[5][0], ad, b0.x); ffma2(acc[5][1], ad, b0.y);
            ffma2(acc[5][2], ad, b1.x); ffma2(acc[5][3], ad, b1.y);
            ad = pack2(a1.z, a1.z);
            ffma2(acc[6][0], ad, b0.x); ffma2(acc[6][1], ad, b0.y);
            ffma2(acc[6][2], ad, b1.x); ffma2(acc[6][3], ad, b1.y);
            ad = pack2(a1.w, a1.w);
            ffma2(acc[7][0], ad, b0.x); ffma2(acc[7][1], ad, b0.y);
            ffma2(acc[7][2], ad, b1.x); ffma2(acc[7][3], ad, b1.y);
        }
        __syncthreads();
    }

#pragma unroll
    for (int i = 0; i < 8; i++) {
        float* crow = C + (size_t)(m0 + ty * 8 + i) * N + n0 + tx * 8;
#pragma unroll
        for (int j2 = 0; j2 < 4; j2++) {
            float2 v = unpk(acc[i][j2]);
            int n = n0 + tx * 8 + j2 * 2;
            float b1v = bias1[n], b2v = bias1[n + 1];
            if (bias2) { b1v += bias2[n]; b2v += bias2[n + 1]; }
            crow[j2 * 2]     = v.x + b1v;
            crow[j2 * 2 + 1] = v.y + b2v;
        }
    }
}

// ---------------------------------------------------------------------------
// Persistent recurrence kernel: 256 blocks (64 unit-blocks x 2 chain-tiles x
// 2 dirs), 256 threads. Each block owns 8 units (all 4 gates) with weights in
// smem; 32 steps separated by a global atomic barrier.
// Thread map: tx = threadIdx.x & 7 -> unit within block; ty = tid >> 3 ->
// chain group (4 chains). acc2[gate][chainpair] via fma.rn.f32x2.
// ---------------------------------------------------------------------------
#define WS_STRIDE 36
#define HS_STRIDE 132
#define SMEM_WS   (512 * WS_STRIDE)
#define SMEM_HS   (32 * HS_STRIDE)
#define SMEM_PER  ((SMEM_WS + SMEM_HS + 128) * 4)

__global__ __launch_bounds__(256, 2)
void lstm_persist(const float* __restrict__ Whh_f,
                  const float* __restrict__ Whh_b,
                  const float* __restrict__ Xf_,
                  const float* __restrict__ Xb_)
{
    extern __shared__ float sm[];
    float* ws = sm;                       // [k][j*4+g], stride 36
    float* hs = sm + SMEM_WS;             // [kk][chain], stride 132
    int*   chmeta = (int*)(sm + SMEM_WS + SMEM_HS);   // [128]

    const int ub  = blockIdx.x;           // 0..63
    const int ct  = blockIdx.y;           // 0..1
    const int dir = blockIdx.z;           // 0..1
    const int tid = threadIdx.x;
    const int tx  = tid & 7;              // unit within block
    const int ty  = tid >> 3;             // chain group
    const int u0  = ub * 8;
    const int ug  = u0 + tx;
    const int c0  = ty * 4;

    const float* Whh = dir ? Whh_b : Whh_f;
    const float* Xd  = dir ? Xb_  : Xf_;
    float* Cst = dir ? g_Cb : g_Cf;
    float* Ad  = dir ? g_Ab : g_Af;

    // cache weight slice: ws[k][j*4+g] = Whh[(g*512 + u0+j)*512 + k]
#pragma unroll 4
    for (int r = 0; r < 32; r++) {
        int g = r & 3, j = r >> 2;
        const float* src = Whh + (size_t)(g * 512 + u0 + j) * 512;
        for (int k = tid; k < 512; k += 256)
            ws[k * WS_STRIDE + r] = src[k];
    }
    __syncthreads();

    for (int s = 0; s < 32; s++) {
        const int L = s + 1;
        const int half = 4 * L;           // chains per chain-tile
        const int mbase = ct * half;
        const int t = dir ? (31 - s) : s;
        const float* Hrd = dir ? ((s & 1) ? g_Hb1 : g_Hb0)
                               : ((s & 1) ? g_Hf1 : g_Hf0);
        float* Hwr = dir ? ((s & 1) ? g_Hb0 : g_Hb1)
                         : ((s & 1) ? g_Hf0 : g_Hf1);

        // chain metadata for this tile
        for (int c = tid; c < half; c += 256) {
            int m = mbase + c;
            int bb = m / L, j = m - bb * L;
            int slot, nw;
            if (dir == 0) { slot = bb * 32 + j;       nw = (j == s); }
            else          { slot = bb * 32 + (t + j); nw = (j == 0); }
            chmeta[c] = slot * 2 + nw;
        }
        __syncthreads();

        ull acc[4][2];
#pragma unroll
        for (int g = 0; g < 4; g++) { acc[g][0] = 0ull; acc[g][1] = 0ull; }

        for (int k0 = 0; k0 < 512; k0 += 32) {
            // stage h chunk (bypass L1: written by other blocks last step)
            for (int c = (tid >> 3); c < half; c += 32) {
                int mt = chmeta[c];
                int slot = mt >> 1;
                int kb = (tid & 7) * 4;
                float4 v;
                if (mt & 1) v = make_float4(0.f, 0.f, 0.f, 0.f);
                else        v = __ldcg((const float4*)&Hrd[slot * 512 + k0 + kb]);
                hs[(kb + 0) * HS_STRIDE + c] = v.x;
                hs[(kb + 1) * HS_STRIDE + c] = v.y;
                hs[(kb + 2) * HS_STRIDE + c] = v.z;
                hs[(kb + 3) * HS_STRIDE + c] = v.w;
            }
            __syncthreads();
#pragma unroll
            for (int kk = 0; kk < 32; kk++) {
                float4 w4 = *(const float4*)&ws[(k0 + kk) * WS_STRIDE + tx * 4];
                ulonglong2 hq = *(const ulonglong2*)&hs[kk * HS_STRIDE + c0];
                ull wd;
                wd = pack2(w4.x, w4.x); ffma2(acc[0][0], wd, hq.x); ffma2(acc[0][1], wd, hq.y);
                wd = pack2(w4.y, w4.y); ffma2(acc[1][0], wd, hq.x); ffma2(acc[1][1], wd, hq.y);
                wd = pack2(w4.z, w4.z); ffma2(acc[2][0], wd, hq.x); ffma2(acc[2][1], wd, hq.y);
                wd = pack2(w4.w, w4.w); ffma2(acc[3][0], wd, hq.x); ffma2(acc[3][1], wd, hq.y);
            }
            __syncthreads();
        }

        // epilogue: this thread handles unit ug for chains c0..c0+3
        if (c0 < half) {
            float2 ga[4][2];
#pragma unroll
            for (int g = 0; g < 4; g++) {
                ga[g][0] = unpk(acc[g][0]);
                ga[g][1] = unpk(acc[g][1]);
            }
#pragma unroll
            for (int i = 0; i < 4; i++) {
                int c = c0 + i;
                int mt = chmeta[c];
                int slot = mt >> 1;
                bool nw = mt & 1;
                int bb = slot >> 5;
                const float* Xrow = Xd + (size_t)(bb * 32 + t) * 2048;
                int p = i >> 1;
                float gi = ((i & 1) ? ga[0][p].y : ga[0][p].x) + Xrow[ug];
                float gf = ((i & 1) ? ga[1][p].y : ga[1][p].x) + Xrow[512 + ug];
                float gg = ((i & 1) ? ga[2][p].y : ga[2][p].x) + Xrow[1024 + ug];
                float go = ((i & 1) ? ga[3][p].y : ga[3][p].x) + Xrow[1536 + ug];
                float cprev = nw ? 0.f : __ldcg(&Cst[slot * 512 + ug]);
                float ig = 1.f / (1.f + __expf(-gi));
                float fg = 1.f / (1.f + __expf(-gf));
                float og = 1.f / (1.f + __expf(-go));
                float gt = tanhf(gg);
                float cc = fg * cprev + ig * gt;
                float hh = og * tanhf(cc);
                Cst[slot * 512 + ug] = cc;
                Hwr[slot * 512 + ug] = hh;
                int tprev = dir ? (t + 1) : (t - 1);
                float ap = nw ? 0.f
                              : __ldcg(&Ad[((size_t)slot * 32 + tprev) * 512 + ug]);
                Ad[((size_t)slot * 32 + t) * 512 + ug] = ap + hh;
            }
        }

        // grid barrier between steps
        __syncthreads();
        if (tid == 0) {
            __threadfence();
            unsigned arr = atomicAdd(&g_barrier[s], 1) + 1;
            if (arr < 256u) {
                while (((volatile unsigned*)g_barrier)[s] < 256u) { }
            }
        }
        __syncthreads();
    }
}

// ---------------------------------------------------------------------------
// Build per-span mean vectors
// ---------------------------------------------------------------------------
__global__ __launch_bounds__(256)
void mean_kernel()
{
    int sidx = blockIdx.x;          // 0..495 (ordered by k then start p)
    int b = blockIdx.y;
    int k = 1, off = 0;
    while (off + (32 - k) <= sidx) { off += (32 - k); k++; }
    int p = sidx - off;
    int q = p + k;
    float inv = 1.f / (float)(k + 1);

    int tid = threadIdx.x;
    float* dst = g_Mean + (size_t)(b * 496 + sidx) * 1024;
    const float* af = g_Af + (((size_t)(b * 32 + p)) * 32 + q) * 512;
    const float* ab = g_Ab + (((size_t)(b * 32 + q)) * 32 + p) * 512;
    for (int uu = tid; uu < 512; uu += 256) {
        dst[uu]       = af[uu] * inv;
        dst[512 + uu] = ab[uu] * inv;
    }
}

// ---------------------------------------------------------------------------
extern "C" void kernel_launch(void* const* d_in, const int* in_sizes, int n_in,
                              void* d_out, int out_size)
{
    const int*   x     = (const int*)  d_in[0];
    const float* emb   = (const float*)d_in[2];
    const float* Wih_f = (const float*)d_in[3];
    const float* Whh_f = (const float*)d_in[4];
    const float* bih_f = (const float*)d_in[5];
    const float* bhh_f = (const float*)d_in[6];
    const float* Wih_b = (const float*)d_in[7];
    const float* Whh_b = (const float*)d_in[8];
    const float* bih_b = (const float*)d_in[9];
    const float* bhh_b = (const float*)d_in[10];
    const float* Wout  = (const float*)d_in[11];
    const float* bout  = (const float*)d_in[12];
    float* out = (float*)d_out;

    static int smem_set = 0;
    if (!smem_set) {
        cudaFuncSetAttribute(lstm_persist,
                             cudaFuncAttributeMaxDynamicSharedMemorySize,
                             SMEM_PER);
        smem_set = 1;
    }

    dim3 blk(256);

    // barrier counters must start at 0 every replay
    zero_bar_kernel<<<1, 32>>>();

    // 1) input-gate precompute (gathered GEMM): [256,512] @ [512,2048]^T
    gemm_kernel<<<dim3(16, 2), blk>>>(emb, x, Wih_f, bih_f, bhh_f, nullptr,
                                      256, 2048, 512, 0);
    gemm_kernel<<<dim3(16, 2), blk>>>(emb, x, Wih_b, bih_b, bhh_b, nullptr,
                                      256, 2048, 512, 1);

    // 2) recurrence: one persistent launch, 32 steps inside
    float* Xf_p; float* Xb_p;
    cudaGetSymbolAddress((void**)&Xf_p, g_Xf);
    cudaGetSymbolAddress((void**)&Xb_p, g_Xb);
    lstm_persist<<<dim3(64, 2, 2), blk, SMEM_PER>>>(Whh_f, Whh_b, Xf_p, Xb_p);

    // 3) span means
    mean_kernel<<<dim3(496, 8), blk>>>();

    // 4) projection GEMM: [3968,1024] @ [1024,7680]^T -> d_out
    gemm_kernel<<<dim3(60, 31), blk>>>(nullptr, nullptr, Wout, bout, nullptr,
                                       out, 3968, 7680, 1024, 2);
}

// round 9
// speedup vs baseline: 1.7446x; 1.6674x over previous
#include <cuda_runtime.h>
#include <cuda_bf16.h>
#include <cstdint>

// ---------------------------------------------------------------------------
// SRNN text encoder:
//   1) X[b][t][4H] = emb[x[b,t]] @ Wih^T + (bih+bhh)     (both directions, fp32)
//   2) persistent recurrence kernel (fp32, weights in smem, grid barrier/step)
//   3) span means + bf16 hi/lo split  ->  A_cat[3968,3072]
//      Wout bf16 hi/lo split          ->  B_cat[7680,3072]   ([Mh|Mh|Ml]x[Wh|Wl|Wh])
//   4) out = A_cat @ B_cat^T + bout   via mma.sync bf16 (HMMA; tcgen05 is
//      unavailable: harness compiles for compute_103, not sm_103a)
// ---------------------------------------------------------------------------

#define NB    8
#define NT    32
#define HD    512
#define G4    2048
#define MROWS 3968
#define NOUT  7680
#define KCAT  3072

typedef unsigned long long ull;

__device__ float g_Xf[NB*NT*G4];
__device__ float g_Xb[NB*NT*G4];
__device__ float g_Af[NB*NT*NT*HD];
__device__ float g_Ab[NB*NT*NT*HD];
__device__ float g_Hf0[NB*NT*HD];
__device__ float g_Hf1[NB*NT*HD];
__device__ float g_Hb0[NB*NT*HD];
__device__ float g_Hb1[NB*NT*HD];
__device__ float g_Cf[NB*NT*HD];
__device__ float g_Cb[NB*NT*HD];
__device__ unsigned g_barrier[32];
__device__ __nv_bfloat16 g_Acat[(size_t)MROWS*KCAT];
__device__ __nv_bfloat16 g_Bcat[(size_t)NOUT*KCAT];

// ---- packed fp32 helpers ---------------------------------------------------
__device__ __forceinline__ void ffma2(ull &acc, ull a, ull b) {
    asm("fma.rn.f32x2 %0, %1, %2, %0;" : "+l"(acc) : "l"(a), "l"(b));
}
__device__ __forceinline__ ull pack2(float x, float y) {
    ull r; asm("mov.b64 %0, {%1, %2};" : "=l"(r) : "f"(x), "f"(y)); return r;
}
__device__ __forceinline__ float2 unpk(ull v) {
    float2 r; asm("mov.b64 {%0, %1}, %2;" : "=f"(r.x), "=f"(r.y) : "l"(v)); return r;
}

// ---- mma.sync helpers (baseline PTX, no sm_103a-gated features) ------------
__device__ __forceinline__ void ldsm4(uint32_t &r0, uint32_t &r1, uint32_t &r2,
                                      uint32_t &r3, uint32_t saddr) {
    asm volatile("ldmatrix.sync.aligned.m8n8.x4.shared.b16 {%0,%1,%2,%3}, [%4];"
                 : "=r"(r0), "=r"(r1), "=r"(r2), "=r"(r3) : "r"(saddr));
}
__device__ __forceinline__ void mma16816(float* c, const uint32_t* a,
                                         uint32_t b0, uint32_t b1) {
    asm volatile("mma.sync.aligned.m16n8k16.row.col.f32.bf16.bf16.f32 "
                 "{%0,%1,%2,%3}, {%4,%5,%6,%7}, {%8,%9}, {%0,%1,%2,%3};"
                 : "+f"(c[0]), "+f"(c[1]), "+f"(c[2]), "+f"(c[3])
                 : "r"(a[0]), "r"(a[1]), "r"(a[2]), "r"(a[3]), "r"(b0), "r"(b1));
}

// ---------------------------------------------------------------------------
__global__ void zero_bar_kernel() {
    if (threadIdx.x < 32) g_barrier[threadIdx.x] = 0;
}

// ---------------------------------------------------------------------------
// gathered fp32 GEMM for X precompute: C[M,N] = emb[x[.]] @ W^T + b1 + b2
// ---------------------------------------------------------------------------
__global__ __launch_bounds__(256)
void gemm_kernel(const float* __restrict__ A, const int* __restrict__ rowidx,
                 const float* __restrict__ Bm, const float* __restrict__ bias1,
                 const float* __restrict__ bias2, float* __restrict__ C,
                 int M, int N, int K)
{
    __shared__ float As[8][128];
    __shared__ float Bs[8][128];
    int tid = threadIdx.x;
    int tx = tid & 15, ty = tid >> 4;
    int m0 = blockIdx.y * 128, n0 = blockIdx.x * 128;

    ull acc[8][4];
#pragma unroll
    for (int i = 0; i < 8; i++)
#pragma unroll
        for (int j = 0; j < 4; j++) acc[i][j] = 0ull;

    for (int k0 = 0; k0 < K; k0 += 8) {
#pragma unroll
        for (int r = 0; r < 4; r++) {
            int e = r * 256 + tid;
            int kk = e & 7, row = e >> 3;
            int ar = rowidx[m0 + row];
            As[kk][row] = A[(size_t)ar * K + k0 + kk];
            Bs[kk][row] = Bm[(size_t)(n0 + row) * K + k0 + kk];
        }
        __syncthreads();
#pragma unroll
        for (int kk = 0; kk < 8; kk++) {
            float4 a0 = *(const float4*)&As[kk][ty * 8];
            float4 a1 = *(const float4*)&As[kk][ty * 8 + 4];
            ulonglong2 b0 = *(const ulonglong2*)&Bs[kk][tx * 8];
            ulonglong2 b1 = *(const ulonglong2*)&Bs[kk][tx * 8 + 4];
            float av[8] = {a0.x, a0.y, a0.z, a0.w, a1.x, a1.y, a1.z, a1.w};
#pragma unroll
            for (int i = 0; i < 8; i++) {
                ull ad = pack2(av[i], av[i]);
                ffma2(acc[i][0], ad, b0.x); ffma2(acc[i][1], ad, b0.y);
                ffma2(acc[i][2], ad, b1.x); ffma2(acc[i][3], ad, b1.y);
            }
        }
        __syncthreads();
    }
#pragma unroll
    for (int i = 0; i < 8; i++) {
        float* crow = C + (size_t)(m0 + ty * 8 + i) * N + n0 + tx * 8;
#pragma unroll
        for (int j2 = 0; j2 < 4; j2++) {
            float2 v = unpk(acc[i][j2]);
            int n = n0 + tx * 8 + j2 * 2;
            crow[j2 * 2]     = v.x + bias1[n] + bias2[n];
            crow[j2 * 2 + 1] = v.y + bias1[n + 1] + bias2[n + 1];
        }
    }
}

// ---------------------------------------------------------------------------
// Persistent recurrence (weights resident in smem; 32 steps, grid barrier)
// ---------------------------------------------------------------------------
#define WS_STRIDE 36
#define HS_STRIDE 132
#define SMEM_WS   (512 * WS_STRIDE)
#define SMEM_HS   (32 * HS_STRIDE)
#define SMEM_PER  ((SMEM_WS + SMEM_HS + 128) * 4)

__global__ __launch_bounds__(256, 2)
void lstm_persist(const float* __restrict__ Whh_f,
                  const float* __restrict__ Whh_b,
                  const float* __restrict__ Xf_,
                  const float* __restrict__ Xb_)
{
    extern __shared__ float sm[];
    float* ws = sm;
    float* hs = sm + SMEM_WS;
    int*   chmeta = (int*)(sm + SMEM_WS + SMEM_HS);

    const int ub  = blockIdx.x;
    const int ct  = blockIdx.y;
    const int dir = blockIdx.z;
    const int tid = threadIdx.x;
    const int tx  = tid & 7;
    const int ty  = tid >> 3;
    const int u0  = ub * 8;
    const int ug  = u0 + tx;
    const int c0  = ty * 4;

    const float* Whh = dir ? Whh_b : Whh_f;
    const float* Xd  = dir ? Xb_  : Xf_;
    float* Cst = dir ? g_Cb : g_Cf;
    float* Ad  = dir ? g_Ab : g_Af;

#pragma unroll 4
    for (int r = 0; r < 32; r++) {
        int g = r & 3, j = r >> 2;
        const float* src = Whh + (size_t)(g * 512 + u0 + j) * 512;
        for (int k = tid; k < 512; k += 256)
            ws[k * WS_STRIDE + r] = src[k];
    }
    __syncthreads();

    for (int s = 0; s < 32; s++) {
        const int L = s + 1;
        const int half = 4 * L;
        const int mbase = ct * half;
        const int t = dir ? (31 - s) : s;
        const float* Hrd = dir ? ((s & 1) ? g_Hb1 : g_Hb0)
                               : ((s & 1) ? g_Hf1 : g_Hf0);
        float* Hwr = dir ? ((s & 1) ? g_Hb0 : g_Hb1)
                         : ((s & 1) ? g_Hf0 : g_Hf1);

        for (int c = tid; c < half; c += 256) {
            int m = mbase + c;
            int bb = m / L, j = m - bb * L;
            int slot, nw;
            if (dir == 0) { slot = bb * 32 + j;       nw = (j == s); }
            else          { slot = bb * 32 + (t + j); nw = (j == 0); }
            chmeta[c] = slot * 2 + nw;
        }
        __syncthreads();

        ull acc[4][2];
#pragma unroll
        for (int g = 0; g < 4; g++) { acc[g][0] = 0ull; acc[g][1] = 0ull; }

        const bool live = (c0 < half);
        for (int k0 = 0; k0 < 512; k0 += 32) {
            for (int c = (tid >> 3); c < half; c += 32) {
                int mt = chmeta[c];
                int slot = mt >> 1;
                int kb = (tid & 7) * 4;
                float4 v;
                if (mt & 1) v = make_float4(0.f, 0.f, 0.f, 0.f);
                else        v = __ldcg((const float4*)&Hrd[slot * 512 + k0 + kb]);
                hs[(kb + 0) * HS_STRIDE + c] = v.x;
                hs[(kb + 1) * HS_STRIDE + c] = v.y;
                hs[(kb + 2) * HS_STRIDE + c] = v.z;
                hs[(kb + 3) * HS_STRIDE + c] = v.w;
            }
            __syncthreads();
            if (live) {
#pragma unroll
                for (int kk = 0; kk < 32; kk++) {
                    float4 w4 = *(const float4*)&ws[(k0 + kk) * WS_STRIDE + tx * 4];
                    ulonglong2 hq = *(const ulonglong2*)&hs[kk * HS_STRIDE + c0];
                    ull wd;
                    wd = pack2(w4.x, w4.x); ffma2(acc[0][0], wd, hq.x); ffma2(acc[0][1], wd, hq.y);
                    wd = pack2(w4.y, w4.y); ffma2(acc[1][0], wd, hq.x); ffma2(acc[1][1], wd, hq.y);
                    wd = pack2(w4.z, w4.z); ffma2(acc[2][0], wd, hq.x); ffma2(acc[2][1], wd, hq.y);
                    wd = pack2(w4.w, w4.w); ffma2(acc[3][0], wd, hq.x); ffma2(acc[3][1], wd, hq.y);
                }
            }
            __syncthreads();
        }

        if (live) {
            float2 ga[4][2];
#pragma unroll
            for (int g = 0; g < 4; g++) {
                ga[g][0] = unpk(acc[g][0]);
                ga[g][1] = unpk(acc[g][1]);
            }
#pragma unroll
            for (int i = 0; i < 4; i++) {
                int c = c0 + i;
                if (c >= half) continue;
                int mt = chmeta[c];
                int slot = mt >> 1;
                bool nw = mt & 1;
                int bb = slot >> 5;
                const float* Xrow = Xd + (size_t)(bb * 32 + t) * 2048;
                int p = i >> 1;
                float gi = ((i & 1) ? ga[0][p].y : ga[0][p].x) + Xrow[ug];
                float gf = ((i & 1) ? ga[1][p].y : ga[1][p].x) + Xrow[512 + ug];
                float gg = ((i & 1) ? ga[2][p].y : ga[2][p].x) + Xrow[1024 + ug];
                float go = ((i & 1) ? ga[3][p].y : ga[3][p].x) + Xrow[1536 + ug];
                float cprev = nw ? 0.f : __ldcg(&Cst[slot * 512 + ug]);
                float ig = 1.f / (1.f + __expf(-gi));
                float fg = 1.f / (1.f + __expf(-gf));
                float og = 1.f / (1.f + __expf(-go));
                float gt = tanhf(gg);
                float cc = fg * cprev + ig * gt;
                float hh = og * tanhf(cc);
                Cst[slot * 512 + ug] = cc;
                Hwr[slot * 512 + ug] = hh;
                int tprev = dir ? (t + 1) : (t - 1);
                float ap = nw ? 0.f
                              : __ldcg(&Ad[((size_t)slot * 32 + tprev) * 512 + ug]);
                Ad[((size_t)slot * 32 + t) * 512 + ug] = ap + hh;
            }
        }

        __syncthreads();
        if (tid == 0) {
            __threadfence();
            unsigned arr = atomicAdd(&g_barrier[s], 1) + 1;
            if (arr < 256u) {
                while (((volatile unsigned*)g_barrier)[s] < 256u) { }
            }
        }
        __syncthreads();
    }
}

// ---------------------------------------------------------------------------
// span means -> bf16 hi/lo split into A_cat  ([Mh | Mh | Ml])
// ---------------------------------------------------------------------------
__global__ __launch_bounds__(256)
void mean_split_kernel()
{
    int sidx = blockIdx.x;
    int b = blockIdx.y;
    int k = 1, off = 0;
    while (off + (32 - k) <= sidx) { off += (32 - k); k++; }
    int p = sidx - off;
    int q = p + k;
    float inv = 1.f / (float)(k + 1);

    int tid = threadIdx.x;
    __nv_bfloat16* dst = g_Acat + (size_t)(b * 496 + sidx) * KCAT;
    const float* af = g_Af + (((size_t)(b * 32 + p)) * 32 + q) * 512;
    const float* ab = g_Ab + (((size_t)(b * 32 + q)) * 32 + p) * 512;
    for (int uu = tid; uu < 512; uu += 256) {
        float f1 = af[uu] * inv;
        __nv_bfloat16 h1 = __float2bfloat16(f1);
        __nv_bfloat16 l1 = __float2bfloat16(f1 - __bfloat162float(h1));
        dst[uu] = h1; dst[1024 + uu] = h1; dst[2048 + uu] = l1;
        float f2 = ab[uu] * inv;
        __nv_bfloat16 h2 = __float2bfloat16(f2);
        __nv_bfloat16 l2 = __float2bfloat16(f2 - __bfloat162float(h2));
        dst[512 + uu] = h2; dst[1536 + uu] = h2; dst[2560 + uu] = l2;
    }
}

// ---------------------------------------------------------------------------
// Wout bf16 hi/lo split into B_cat  ([Wh | Wl | Wh])
// ---------------------------------------------------------------------------
__global__ __launch_bounds__(256)
void wout_split_kernel(const float* __restrict__ Wout)
{
    int n = blockIdx.x;
    __nv_bfloat16* dst = g_Bcat + (size_t)n * KCAT;
    const float* src = Wout + (size_t)n * 1024;
    for (int k = threadIdx.x; k < 1024; k += 256) {
        float w = src[k];
        __nv_bfloat16 h = __float2bfloat16(w);
        __nv_bfloat16 l = __float2bfloat16(w - __bfloat162float(h));
        dst[k] = h; dst[1024 + k] = l; dst[2048 + k] = h;
    }
}

// ---------------------------------------------------------------------------
// Projection via mma.sync (bf16, fp32 accum):
//   out[3968,7680] = A_cat @ B_cat^T + bout
// Block: 128x128 tile, 256 thr / 8 warps (warp tile 64x32),
// K-chunk 32, double-buffered smem, rows strided 40 bf16 (80B: conflict-free
// ldmatrix — {r*80 mod 128} covers all 8 16B segments).
// ---------------------------------------------------------------------------
#define PSTRIDE 40
#define PCHUNK  32
#define NCHUNK  (KCAT / PCHUNK)   // 96

__global__ __launch_bounds__(256, 2)
void proj_mma_kernel(const float* __restrict__ bout, float* __restrict__ out)
{
    __shared__ __nv_bfloat16 As[2][128 * PSTRIDE];
    __shared__ __nv_bfloat16 Bs[2][128 * PSTRIDE];

    const int tid = threadIdx.x;
    const int wid = tid >> 5;
    const int lane = tid & 31;
    const int wm = wid & 1;          // warp row (64 m each)
    const int wn = wid >> 1;         // warp col (32 n each)
    const int m0 = blockIdx.y * 128;
    const int n0 = blockIdx.x * 128;

    const __nv_bfloat16* Ag = g_Acat + (size_t)m0 * KCAT;
    const __nv_bfloat16* Bg = g_Bcat + (size_t)n0 * KCAT;

    // staging map: thread -> row tid>>1, 32B segment (tid&1)
    const int srow = tid >> 1;
    const int scol = (tid & 1) * 16;             // element offset (bf16)
    const __nv_bfloat16* agp = Ag + (size_t)srow * KCAT + scol;
    const __nv_bfloat16* bgp = Bg + (size_t)srow * KCAT + scol;
    const int ssoff = srow * PSTRIDE + scol;

    float acc[4][4][4];
#pragma unroll
    for (int i = 0; i < 4; i++)
#pragma unroll
        for (int j = 0; j < 4; j++)
#pragma unroll
            for (int r = 0; r < 4; r++) acc[i][j][r] = 0.f;

    // ldmatrix shared addresses (byte offsets within buffer)
    uint32_t a_base = (uint32_t)__cvta_generic_to_shared(&As[0][0]);
    uint32_t b_base = (uint32_t)__cvta_generic_to_shared(&Bs[0][0]);
    const uint32_t bufA = 128 * PSTRIDE * 2;     // bytes per A buffer
    // A frag addr: row = wm*64 + i*16 + (lane&15), col = kb + (lane>>4)*8
    const int a_row = wm * 64 + (lane & 15);
    const int a_col = (lane >> 4) * 8;
    // B frag addr: row = wn*32 + j*16 + ((lane>>4)<<3) + (lane&7),
    //              col = kb + ((lane>>3)&1)*8
    const int b_row = wn * 32 + ((lane >> 4) << 3) + (lane & 7);
    const int b_col = ((lane >> 3) & 1) * 8;

    // prologue: stage chunk 0
    {
        uint4 av0 = __ldg((const uint4*)(agp));
        uint4 av1 = __ldg((const uint4*)(agp + 8));
        uint4 bv0 = __ldg((const uint4*)(bgp));
        uint4 bv1 = __ldg((const uint4*)(bgp + 8));
        *(uint4*)&As[0][ssoff]     = av0;
        *(uint4*)&As[0][ssoff + 8] = av1;
        *(uint4*)&Bs[0][ssoff]     = bv0;
        *(uint4*)&Bs[0][ssoff + 8] = bv1;
    }
    __syncthreads();

    for (int c = 0; c < NCHUNK; c++) {
        const int cur = c & 1;
        uint4 av0, av1, bv0, bv1;
        if (c + 1 < NCHUNK) {
            const __nv_bfloat16* ag = agp + (c + 1) * PCHUNK;
            const __nv_bfloat16* bg = bgp + (c + 1) * PCHUNK;
            av0 = __ldg((const uint4*)(ag));
            av1 = __ldg((const uint4*)(ag + 8));
            bv0 = __ldg((const uint4*)(bg));
            bv1 = __ldg((const uint4*)(bg + 8));
        }

        uint32_t abuf = a_base + cur * bufA;
        uint32_t bbuf = b_base + cur * bufA;
#pragma unroll
        for (int kb = 0; kb < PCHUNK; kb += 16) {
            uint32_t a[4][4];
            uint32_t b[2][4];
#pragma unroll
            for (int i = 0; i < 4; i++)
                ldsm4(a[i][0], a[i][1], a[i][2], a[i][3],
                      abuf + ((a_row + i * 16) * PSTRIDE + kb + a_col) * 2);
#pragma unroll
            for (int j = 0; j < 2; j++)
                ldsm4(b[j][0], b[j][1], b[j][2], b[j][3],
                      bbuf + ((b_row + j * 16) * PSTRIDE + kb + b_col) * 2);
#pragma unroll
            for (int i = 0; i < 4; i++) {
#pragma unroll
                for (int j = 0; j < 2; j++) {
                    mma16816(acc[i][j * 2],     a[i], b[j][0], b[j][1]);
                    mma16816(acc[i][j * 2 + 1], a[i], b[j][2], b[j][3]);
                }
            }
        }
        __syncthreads();
        if (c + 1 < NCHUNK) {
            const int nxt = cur ^ 1;
            *(uint4*)&As[nxt][ssoff]     = av0;
            *(uint4*)&As[nxt][ssoff + 8] = av1;
            *(uint4*)&Bs[nxt][ssoff]     = bv0;
            *(uint4*)&Bs[nxt][ssoff + 8] = bv1;
            __syncthreads();
        }
    }

    // epilogue: D rows m0+wm*64+i*16+(lane>>2)(+8), cols n0+wn*32+jj*8+(lane&3)*2
#pragma unroll
    for (int i = 0; i < 4; i++) {
        int row = m0 + wm * 64 + i * 16 + (lane >> 2);
#pragma unroll
        for (int jj = 0; jj < 4; jj++) {
            int col = n0 + wn * 32 + jj * 8 + (lane & 3) * 2;
            float2 bo = *(const float2*)&bout[col];
            float2 v0 = make_float2(acc[i][jj][0] + bo.x, acc[i][jj][1] + bo.y);
            float2 v1 = make_float2(acc[i][jj][2] + bo.x, acc[i][jj][3] + bo.y);
            *(float2*)&out[(size_t)row * NOUT + col] = v0;
            *(float2*)&out[(size_t)(row + 8) * NOUT + col] = v1;
        }
    }
}

// ---------------------------------------------------------------------------
extern "C" void kernel_launch(void* const* d_in, const int* in_sizes, int n_in,
                              void* d_out, int out_size)
{
    const int*   x     = (const int*)  d_in[0];
    const float* emb   = (const float*)d_in[2];
    const float* Wih_f = (const float*)d_in[3];
    const float* Whh_f = (const float*)d_in[4];
    const float* bih_f = (const float*)d_in[5];
    const float* bhh_f = (const float*)d_in[6];
    const float* Wih_b = (const float*)d_in[7];
    const float* Whh_b = (const float*)d_in[8];
    const float* bih_b = (const float*)d_in[9];
    const float* bhh_b = (const float*)d_in[10];
    const float* Wout  = (const float*)d_in[11];
    const float* bout  = (const float*)d_in[12];
    float* out = (float*)d_out;

    static int attr_set = 0;
    if (!attr_set) {
        cudaFuncSetAttribute(lstm_persist,
                             cudaFuncAttributeMaxDynamicSharedMemorySize, SMEM_PER);
        attr_set = 1;
    }

    float *Xf_p, *Xb_p;
    cudaGetSymbolAddress((void**)&Xf_p, g_Xf);
    cudaGetSymbolAddress((void**)&Xb_p, g_Xb);

    dim3 blk(256);

    zero_bar_kernel<<<1, 32>>>();
    wout_split_kernel<<<NOUT, blk>>>(Wout);

    gemm_kernel<<<dim3(16, 2), blk>>>(emb, x, Wih_f, bih_f, bhh_f, Xf_p,
                                      256, 2048, 512);
    gemm_kernel<<<dim3(16, 2), blk>>>(emb, x, Wih_b, bih_b, bhh_b, Xb_p,
                                      256, 2048, 512);

    lstm_persist<<<dim3(64, 2, 2), blk, SMEM_PER>>>(Whh_f, Whh_b, Xf_p, Xb_p);

    mean_split_kernel<<<dim3(496, 8), blk>>>();

    proj_mma_kernel<<<dim3(60, 31), blk>>>(bout, out);
}

// round 10
// speedup vs baseline: 2.1341x; 1.2232x over previous
#include <cuda_runtime.h>
#include <cuda_fp16.h>
#include <cstdint>

// ---------------------------------------------------------------------------
// SRNN text encoder:
//   1) X[b][t][4H] = emb[x[b,t]] @ Wih^T + (bih+bhh)   (fused dirs, fp32)
//   2) persistent recurrence kernel (fp32, weights in smem, grid barrier/step)
//   3) span means -> fp16 2-term split  A2[3968,2048] = [Mh | Mh*2^-11]
//      Wout       -> fp16 2-term split  B2[7680,2048] = [Wh | (W-Wh)*2^11]
//      (out = Mh*W exactly; dropped Ml*W ~ 2.8e-4 rel, threshold 1e-3)
//   4) out = A2 @ B2^T + bout   via mma.sync fp16 (HMMA)
// ---------------------------------------------------------------------------

#define NB    8
#define NT    32
#define HD    512
#define G4    2048
#define MROWS 3968
#define NOUT  7680
#define KC2   2048

typedef unsigned long long ull;

__device__ float g_Xf[NB*NT*G4];
__device__ float g_Xb[NB*NT*G4];
__device__ float g_Af[NB*NT*NT*HD];
__device__ float g_Ab[NB*NT*NT*HD];
__device__ float g_Hf0[NB*NT*HD];
__device__ float g_Hf1[NB*NT*HD];
__device__ float g_Hb0[NB*NT*HD];
__device__ float g_Hb1[NB*NT*HD];
__device__ float g_Cf[NB*NT*HD];
__device__ float g_Cb[NB*NT*HD];
__device__ unsigned g_barrier[32];
__device__ __half g_Acat[(size_t)MROWS*KC2];
__device__ __half g_Bcat[(size_t)NOUT*KC2];

// ---- packed fp32 helpers ---------------------------------------------------
__device__ __forceinline__ void ffma2(ull &acc, ull a, ull b) {
    asm("fma.rn.f32x2 %0, %1, %2, %0;" : "+l"(acc) : "l"(a), "l"(b));
}
__device__ __forceinline__ ull pack2(float x, float y) {
    ull r; asm("mov.b64 %0, {%1, %2};" : "=l"(r) : "f"(x), "f"(y)); return r;
}
__device__ __forceinline__ float2 unpk(ull v) {
    float2 r; asm("mov.b64 {%0, %1}, %2;" : "=f"(r.x), "=f"(r.y) : "l"(v)); return r;
}

// ---- mma.sync helpers (baseline PTX, no sm_103a-gated features) ------------
__device__ __forceinline__ void ldsm4(uint32_t &r0, uint32_t &r1, uint32_t &r2,
                                      uint32_t &r3, uint32_t saddr) {
    asm volatile("ldmatrix.sync.aligned.m8n8.x4.shared.b16 {%0,%1,%2,%3}, [%4];"
                 : "=r"(r0), "=r"(r1), "=r"(r2), "=r"(r3) : "r"(saddr));
}
__device__ __forceinline__ void mma16816(float* c, const uint32_t* a,
                                         uint32_t b0, uint32_t b1) {
    asm volatile("mma.sync.aligned.m16n8k16.row.col.f32.f16.f16.f32 "
                 "{%0,%1,%2,%3}, {%4,%5,%6,%7}, {%8,%9}, {%0,%1,%2,%3};"
                 : "+f"(c[0]), "+f"(c[1]), "+f"(c[2]), "+f"(c[3])
                 : "r"(a[0]), "r"(a[1]), "r"(a[2]), "r"(a[3]), "r"(b0), "r"(b1));
}

// ---------------------------------------------------------------------------
__global__ void zero_bar_kernel() {
    if (threadIdx.x < 32) g_barrier[threadIdx.x] = 0;
}

// ---------------------------------------------------------------------------
// fused X precompute (both dirs via blockIdx.z):
//   C[z][M=256,N=2048] = emb[x[.]] @ W[z]^T + b1[z] + b2[z]
// Tile 64x128, 128 blocks.
// ---------------------------------------------------------------------------
__global__ __launch_bounds__(256)
void xgemm_kernel(const float* __restrict__ emb, const int* __restrict__ xidx,
                  const float* __restrict__ Wf, const float* __restrict__ Wb,
                  const float* __restrict__ b1f, const float* __restrict__ b2f,
                  const float* __restrict__ b1b, const float* __restrict__ b2b,
                  float* __restrict__ Cf, float* __restrict__ Cb)
{
    const int z = blockIdx.z;
    const float* Bm    = z ? Wb  : Wf;
    const float* bias1 = z ? b1b : b1f;
    const float* bias2 = z ? b2b : b2f;
    float*       C     = z ? Cb  : Cf;

    __shared__ float As[8][64];
    __shared__ float Bs[8][128];

    int tid = threadIdx.x;
    int tx = tid & 15, ty = tid >> 4;
    int m0 = blockIdx.y * 64, n0 = blockIdx.x * 128;

    ull acc[4][4];
#pragma unroll
    for (int i = 0; i < 4; i++)
#pragma unroll
        for (int j = 0; j < 4; j++) acc[i][j] = 0ull;

    for (int k0 = 0; k0 < 512; k0 += 8) {
        {
            int kk = tid & 7, row = tid >> 3;               // rows 0..31
            As[kk][row] = emb[(size_t)xidx[m0 + row] * 512 + k0 + kk];
            int e2 = 256 + tid;
            int kk2 = e2 & 7, row2 = e2 >> 3;               // rows 32..63
            As[kk2][row2] = emb[(size_t)xidx[m0 + row2] * 512 + k0 + kk2];
        }
#pragma unroll
        for (int r = 0; r < 4; r++) {
            int e = r * 256 + tid;
            int kk = e & 7, row = e >> 3;
            Bs[kk][row] = Bm[(size_t)(n0 + row) * 512 + k0 + kk];
        }
        __syncthreads();
#pragma unroll
        for (int kk = 0; kk < 8; kk++) {
            float4 a = *(const float4*)&As[kk][ty * 4];
            ulonglong2 b0 = *(const ulonglong2*)&Bs[kk][tx * 8];
            ulonglong2 b1 = *(const ulonglong2*)&Bs[kk][tx * 8 + 4];
            float av[4] = {a.x, a.y, a.z, a.w};
#pragma unroll
            for (int i = 0; i < 4; i++) {
                ull ad = pack2(av[i], av[i]);
                ffma2(acc[i][0], ad, b0.x); ffma2(acc[i][1], ad, b0.y);
                ffma2(acc[i][2], ad, b1.x); ffma2(acc[i][3], ad, b1.y);
            }
        }
        __syncthreads();
    }
#pragma unroll
    for (int i = 0; i < 4; i++) {
        float* crow = C + (size_t)(m0 + ty * 4 + i) * 2048 + n0 + tx * 8;
#pragma unroll
        for (int j2 = 0; j2 < 4; j2++) {
            float2 v = unpk(acc[i][j2]);
            int n = n0 + tx * 8 + j2 * 2;
            crow[j2 * 2]     = v.x + bias1[n] + bias2[n];
            crow[j2 * 2 + 1] = v.y + bias1[n + 1] + bias2[n + 1];
        }
    }
}

// ---------------------------------------------------------------------------
// Persistent recurrence (weights resident in smem; 32 steps, grid barrier)
// ---------------------------------------------------------------------------
#define WS_STRIDE 36
#define HS_STRIDE 132
#define SMEM_WS   (512 * WS_STRIDE)
#define SMEM_HS   (32 * HS_STRIDE)
#define SMEM_PER  ((SMEM_WS + SMEM_HS + 128) * 4)

__global__ __launch_bounds__(256, 2)
void lstm_persist(const float* __restrict__ Whh_f,
                  const float* __restrict__ Whh_b,
                  const float* __restrict__ Xf_,
                  const float* __restrict__ Xb_)
{
    extern __shared__ float sm[];
    float* ws = sm;
    float* hs = sm + SMEM_WS;
    int*   chmeta = (int*)(sm + SMEM_WS + SMEM_HS);

    const int ub  = blockIdx.x;
    const int ct  = blockIdx.y;
    const int dir = blockIdx.z;
    const int tid = threadIdx.x;
    const int tx  = tid & 7;
    const int ty  = tid >> 3;
    const int u0  = ub * 8;
    const int ug  = u0 + tx;
    const int c0  = ty * 4;

    const float* Whh = dir ? Whh_b : Whh_f;
    const float* Xd  = dir ? Xb_  : Xf_;
    float* Cst = dir ? g_Cb : g_Cf;
    float* Ad  = dir ? g_Ab : g_Af;

#pragma unroll 4
    for (int r = 0; r < 32; r++) {
        int g = r & 3, j = r >> 2;
        const float* src = Whh + (size_t)(g * 512 + u0 + j) * 512;
        for (int k = tid; k < 512; k += 256)
            ws[k * WS_STRIDE + r] = src[k];
    }
    __syncthreads();

    for (int s = 0; s < 32; s++) {
        const int L = s + 1;
        const int half = 4 * L;
        const int mbase = ct * half;
        const int t = dir ? (31 - s) : s;
        const float* Hrd = dir ? ((s & 1) ? g_Hb1 : g_Hb0)
                               : ((s & 1) ? g_Hf1 : g_Hf0);
        float* Hwr = dir ? ((s & 1) ? g_Hb0 : g_Hb1)
                         : ((s & 1) ? g_Hf0 : g_Hf1);

        for (int c = tid; c < half; c += 256) {
            int m = mbase + c;
            int bb = m / L, j = m - bb * L;
            int slot, nw;
            if (dir == 0) { slot = bb * 32 + j;       nw = (j == s); }
            else          { slot = bb * 32 + (t + j); nw = (j == 0); }
            chmeta[c] = slot * 2 + nw;
        }
        __syncthreads();

        ull acc[4][2];
#pragma unroll
        for (int g = 0; g < 4; g++) { acc[g][0] = 0ull; acc[g][1] = 0ull; }

        const bool live = (c0 < half);
        for (int k0 = 0; k0 < 512; k0 += 32) {
            for (int c = (tid >> 3); c < half; c += 32) {
                int mt = chmeta[c];
                int slot = mt >> 1;
                int kb = (tid & 7) * 4;
                float4 v;
                if (mt & 1) v = make_float4(0.f, 0.f, 0.f, 0.f);
                else        v = __ldcg((const float4*)&Hrd[slot * 512 + k0 + kb]);
                hs[(kb + 0) * HS_STRIDE + c] = v.x;
                hs[(kb + 1) * HS_STRIDE + c] = v.y;
                hs[(kb + 2) * HS_STRIDE + c] = v.z;
                hs[(kb + 3) * HS_STRIDE + c] = v.w;
            }
            __syncthreads();
            if (live) {
#pragma unroll
                for (int kk = 0; kk < 32; kk++) {
                    float4 w4 = *(const float4*)&ws[(k0 + kk) * WS_STRIDE + tx * 4];
                    ulonglong2 hq = *(const ulonglong2*)&hs[kk * HS_STRIDE + c0];
                    ull wd;
                    wd = pack2(w4.x, w4.x); ffma2(acc[0][0], wd, hq.x); ffma2(acc[0][1], wd, hq.y);
                    wd = pack2(w4.y, w4.y); ffma2(acc[1][0], wd, hq.x); ffma2(acc[1][1], wd, hq.y);
                    wd = pack2(w4.z, w4.z); ffma2(acc[2][0], wd, hq.x); ffma2(acc[2][1], wd, hq.y);
                    wd = pack2(w4.w, w4.w); ffma2(acc[3][0], wd, hq.x); ffma2(acc[3][1], wd, hq.y);
                }
            }
            __syncthreads();
        }

        if (live) {
            float2 ga[4][2];
#pragma unroll
            for (int g = 0; g < 4; g++) {
                ga[g][0] = unpk(acc[g][0]);
                ga[g][1] = unpk(acc[g][1]);
            }
#pragma unroll
            for (int i = 0; i < 4; i++) {
                int c = c0 + i;
                if (c >= half) continue;
                int mt = chmeta[c];
                int slot = mt >> 1;
                bool nw = mt & 1;
                int bb = slot >> 5;
                const float* Xrow = Xd + (size_t)(bb * 32 + t) * 2048;
                int p = i >> 1;
                float gi = ((i & 1) ? ga[0][p].y : ga[0][p].x) + Xrow[ug];
                float gf = ((i & 1) ? ga[1][p].y : ga[1][p].x) + Xrow[512 + ug];
                float gg = ((i & 1) ? ga[2][p].y : ga[2][p].x) + Xrow[1024 + ug];
                float go = ((i & 1) ? ga[3][p].y : ga[3][p].x) + Xrow[1536 + ug];
                float cprev = nw ? 0.f : __ldcg(&Cst[slot * 512 + ug]);
                float ig = 1.f / (1.f + __expf(-gi));
                float fg = 1.f / (1.f + __expf(-gf));
                float og = 1.f / (1.f + __expf(-go));
                float gt = tanhf(gg);
                float cc = fg * cprev + ig * gt;
                float hh = og * tanhf(cc);
                Cst[slot * 512 + ug] = cc;
                Hwr[slot * 512 + ug] = hh;
                int tprev = dir ? (t + 1) : (t - 1);
                float ap = nw ? 0.f
                              : __ldcg(&Ad[((size_t)slot * 32 + tprev) * 512 + ug]);
                Ad[((size_t)slot * 32 + t) * 512 + ug] = ap + hh;
            }
        }

        __syncthreads();
        if (tid == 0) {
            __threadfence();
            unsigned arr = atomicAdd(&g_barrier[s], 1) + 1;
            if (arr < 256u) {
                while (((volatile unsigned*)g_barrier)[s] < 256u) { }
            }
        }
        __syncthreads();
    }
}

// ---------------------------------------------------------------------------
// span means -> fp16 2-term split:  A2 = [Mh | Mh*2^-11]
// ---------------------------------------------------------------------------
__global__ __launch_bounds__(256)
void mean_split_kernel()
{
    int sidx = blockIdx.x;
    int b = blockIdx.y;
    int k = 1, off = 0;
    while (off + (32 - k) <= sidx) { off += (32 - k); k++; }
    int p = sidx - off;
    int q = p + k;
    float inv = 1.f / (float)(k + 1);

    int tid = threadIdx.x;
    __half* dst = g_Acat + (size_t)(b * 496 + sidx) * KC2;
    const float* af = g_Af + (((size_t)(b * 32 + p)) * 32 + q) * 512;
    const float* ab = g_Ab + (((size_t)(b * 32 + q)) * 32 + p) * 512;
    const float s11 = 1.0f / 2048.0f;     // 2^-11 (exact)
    for (int uu = tid; uu < 512; uu += 256) {
        float f1 = af[uu] * inv;
        __half h1 = __float2half(f1);
        dst[uu]        = h1;
        dst[1024 + uu] = __float2half(__half2float(h1) * s11);
        float f2 = ab[uu] * inv;
        __half h2 = __float2half(f2);
        dst[512 + uu]  = h2;
        dst[1536 + uu] = __float2half(__half2float(h2) * s11);
    }
}

// ---------------------------------------------------------------------------
// Wout fp16 2-term split:  B2 = [Wh | (W - Wh)*2^11]
// ---------------------------------------------------------------------------
__global__ __launch_bounds__(256)
void wout_split_kernel(const float* __restrict__ Wout)
{
    int n = blockIdx.x;
    __half* dst = g_Bcat + (size_t)n * KC2;
    const float* src = Wout + (size_t)n * 1024;
    for (int k = threadIdx.x; k < 1024; k += 256) {
        float w = src[k];
        __half h = __float2half(w);
        dst[k]        = h;
        dst[1024 + k] = __float2half((w - __half2float(h)) * 2048.0f);
    }
}

// ---------------------------------------------------------------------------
// Projection via mma.sync (fp16, fp32 accum):
//   out[3968,7680] = A2 @ B2^T + bout
// Block: 128x128 tile, 256 thr / 8 warps (warp tile 64x32),
// K-chunk 32, double-buffered smem, rows strided 40 halves (80B: conflict-free
// ldmatrix — {r*80 mod 128} covers all 8 16B segments).
// ---------------------------------------------------------------------------
#define PSTRIDE 40
#define PCHUNK  32
#define NCHUNK  (KC2 / PCHUNK)   // 64

__global__ __launch_bounds__(256, 2)
void proj_mma_kernel(const float* __restrict__ bout, float* __restrict__ out)
{
    __shared__ __half As[2][128 * PSTRIDE];
    __shared__ __half Bs[2][128 * PSTRIDE];

    const int tid = threadIdx.x;
    const int wid = tid >> 5;
    const int lane = tid & 31;
    const int wm = wid & 1;          // warp row (64 m each)
    const int wn = wid >> 1;         // warp col (32 n each)
    const int m0 = blockIdx.y * 128;
    const int n0 = blockIdx.x * 128;

    const __half* Ag = g_Acat + (size_t)m0 * KC2;
    const __half* Bg = g_Bcat + (size_t)n0 * KC2;

    const int srow = tid >> 1;
    const int scol = (tid & 1) * 16;
    const __half* agp = Ag + (size_t)srow * KC2 + scol;
    const __half* bgp = Bg + (size_t)srow * KC2 + scol;
    const int ssoff = srow * PSTRIDE + scol;

    float acc[4][4][4];
#pragma unroll
    for (int i = 0; i < 4; i++)
#pragma unroll
        for (int j = 0; j < 4; j++)
#pragma unroll
            for (int r = 0; r < 4; r++) acc[i][j][r] = 0.f;

    uint32_t a_base = (uint32_t)__cvta_generic_to_shared(&As[0][0]);
    uint32_t b_base = (uint32_t)__cvta_generic_to_shared(&Bs[0][0]);
    const uint32_t bufA = 128 * PSTRIDE * 2;
    const int a_row = wm * 64 + (lane & 15);
    const int a_col = (lane >> 4) * 8;
    const int b_row = wn * 32 + ((lane >> 4) << 3) + (lane & 7);
    const int b_col = ((lane >> 3) & 1) * 8;

    {
        uint4 av0 = __ldg((const uint4*)(agp));
        uint4 av1 = __ldg((const uint4*)(agp + 8));
        uint4 bv0 = __ldg((const uint4*)(bgp));
        uint4 bv1 = __ldg((const uint4*)(bgp + 8));
        *(uint4*)&As[0][ssoff]     = av0;
        *(uint4*)&As[0][ssoff + 8] = av1;
        *(uint4*)&Bs[0][ssoff]     = bv0;
        *(uint4*)&Bs[0][ssoff + 8] = bv1;
    }
    __syncthreads();

    for (int c = 0; c < NCHUNK; c++) {
        const int cur = c & 1;
        uint4 av0, av1, bv0, bv1;
        if (c + 1 < NCHUNK) {
            const __half* ag = agp + (c + 1) * PCHUNK;
            const __half* bg = bgp + (c + 1) * PCHUNK;
            av0 = __ldg((const uint4*)(ag));
            av1 = __ldg((const uint4*)(ag + 8));
            bv0 = __ldg((const uint4*)(bg));
            bv1 = __ldg((const uint4*)(bg + 8));
        }

        uint32_t abuf = a_base + cur * bufA;
        uint32_t bbuf = b_base + cur * bufA;
#pragma unroll
        for (int kb = 0; kb < PCHUNK; kb += 16) {
            uint32_t a[4][4];
            uint32_t b[2][4];
#pragma unroll
            for (int i = 0; i < 4; i++)
                ldsm4(a[i][0], a[i][1], a[i][2], a[i][3],
                      abuf + ((a_row + i * 16) * PSTRIDE + kb + a_col) * 2);
#pragma unroll
            for (int j = 0; j < 2; j++)
                ldsm4(b[j][0], b[j][1], b[j][2], b[j][3],
                      bbuf + ((b_row + j * 16) * PSTRIDE + kb + b_col) * 2);
#pragma unroll
            for (int i = 0; i < 4; i++) {
#pragma unroll
                for (int j = 0; j < 2; j++) {
                    mma16816(acc[i][j * 2],     a[i], b[j][0], b[j][1]);
                    mma16816(acc[i][j * 2 + 1], a[i], b[j][2], b[j][3]);
                }
            }
        }
        __syncthreads();
        if (c + 1 < NCHUNK) {
            const int nxt = cur ^ 1;
            *(uint4*)&As[nxt][ssoff]     = av0;
            *(uint4*)&As[nxt][ssoff + 8] = av1;
            *(uint4*)&Bs[nxt][ssoff]     = bv0;
            *(uint4*)&Bs[nxt][ssoff + 8] = bv1;
            __syncthreads();
        }
    }

#pragma unroll
    for (int i = 0; i < 4; i++) {
        int row = m0 + wm * 64 + i * 16 + (lane >> 2);
#pragma unroll
        for (int jj = 0; jj < 4; jj++) {
            int col = n0 + wn * 32 + jj * 8 + (lane & 3) * 2;
            float2 bo = *(const float2*)&bout[col];
            float2 v0 = make_float2(acc[i][jj][0] + bo.x, acc[i][jj][1] + bo.y);
            float2 v1 = make_float2(acc[i][jj][2] + bo.x, acc[i][jj][3] + bo.y);
            *(float2*)&out[(size_t)row * NOUT + col] = v0;
            *(float2*)&out[(size_t)(row + 8) * NOUT + col] = v1;
        }
    }
}

// ---------------------------------------------------------------------------
extern "C" void kernel_launch(void* const* d_in, const int* in_sizes, int n_in,
                              void* d_out, int out_size)
{
    const int*   x     = (const int*)  d_in[0];
    const float* emb   = (const float*)d_in[2];
    const float* Wih_f = (const float*)d_in[3];
    const float* Whh_f = (const float*)d_in[4];
    const float* bih_f = (const float*)d_in[5];
    const float* bhh_f = (const float*)d_in[6];
    const float* Wih_b = (const float*)d_in[7];
    const float* Whh_b = (const float*)d_in[8];
    const float* bih_b = (const float*)d_in[9];
    const float* bhh_b = (const float*)d_in[10];
    const float* Wout  = (const float*)d_in[11];
    const float* bout  = (const float*)d_in[12];
    float* out = (float*)d_out;

    static int attr_set = 0;
    if (!attr_set) {
        cudaFuncSetAttribute(lstm_persist,
                             cudaFuncAttributeMaxDynamicSharedMemorySize, SMEM_PER);
        attr_set = 1;
    }

    float *Xf_p, *Xb_p;
    cudaGetSymbolAddress((void**)&Xf_p, g_Xf);
    cudaGetSymbolAddress((void**)&Xb_p, g_Xb);

    dim3 blk(256);

    zero_bar_kernel<<<1, 32>>>();
    wout_split_kernel<<<NOUT, blk>>>(Wout);

    xgemm_kernel<<<dim3(16, 4, 2), blk>>>(emb, x, Wih_f, Wih_b,
                                          bih_f, bhh_f, bih_b, bhh_b,
                                          Xf_p, Xb_p);

    lstm_persist<<<dim3(64, 2, 2), blk, SMEM_PER>>>(Whh_f, Whh_b, Xf_p, Xb_p);

    mean_split_kernel<<<dim3(496, 8), blk>>>();

    proj_mma_kernel<<<dim3(60, 31), blk>>>(bout, out);
}

// round 11
// speedup vs baseline: 2.5139x; 1.1779x over previous
#include <cuda_runtime.h>
#include <cuda_fp16.h>
#include <cstdint>

// ---------------------------------------------------------------------------
// SRNN text encoder:
//   1) X[b][t][4H] = emb[x[b,t]] @ Wih^T + (bih+bhh)   (fused dirs, fp32)
//   2) recurrence: 32 per-step HMMA kernels.  gates = X + h @ Whh^T computed
//      via 3-term fp16 split (error ~2^-22):  h=hh+hl, W=wh+wl,
//      A3=[hh | hh*2^-11 | hl*2^6], B3=[wh | wl*2^11 | wh*2^-6], K=1536.
//      LSTM cell + cumsum fused in epilogue; h3 double-buffered by parity;
//      new chains read a permanently-zero pad row (no per-replay init).
//   3) span means -> fp16 2-term split  A2[3968,2048]
//      Wout       -> fp16 2-term split  B2[7680,2048]
//   4) out = A2 @ B2^T + bout   via mma.sync fp16
// ---------------------------------------------------------------------------

#define NB    8
#define NT    32
#define HD    512
#define G4    2048
#define MROWS 3968
#define NOUT  7680
#define KC2   2048
#define KR3   1536
#define ZROW  260          // pad row in g_h3, never written => always zero

typedef unsigned long long ull;

__device__ float g_Xf[NB*NT*G4];
__device__ float g_Xb[NB*NT*G4];
__device__ float g_Af[NB*NT*NT*HD];
__device__ float g_Ab[NB*NT*NT*HD];
__device__ float g_Cf[NB*NT*HD];
__device__ float g_Cb[NB*NT*HD];
__device__ __half g_h3[2][2][264][KR3];      // [dir][buf][slot][k]
__device__ __half g_W3[2][2048][KR3];        // [dir][n=u*4+g][k]
__device__ __half g_Acat[(size_t)MROWS*KC2];
__device__ __half g_Bcat[(size_t)NOUT*KC2];

// ---- packed fp32 helpers ---------------------------------------------------
__device__ __forceinline__ void ffma2(ull &acc, ull a, ull b) {
    asm("fma.rn.f32x2 %0, %1, %2, %0;" : "+l"(acc) : "l"(a), "l"(b));
}
__device__ __forceinline__ ull pack2(float x, float y) {
    ull r; asm("mov.b64 %0, {%1, %2};" : "=l"(r) : "f"(x), "f"(y)); return r;
}
__device__ __forceinline__ float2 unpk(ull v) {
    float2 r; asm("mov.b64 {%0, %1}, %2;" : "=f"(r.x), "=f"(r.y) : "l"(v)); return r;
}

// ---- mma.sync helpers ------------------------------------------------------
__device__ __forceinline__ void ldsm4(uint32_t &r0, uint32_t &r1, uint32_t &r2,
                                      uint32_t &r3, uint32_t saddr) {
    asm volatile("ldmatrix.sync.aligned.m8n8.x4.shared.b16 {%0,%1,%2,%3}, [%4];"
                 : "=r"(r0), "=r"(r1), "=r"(r2), "=r"(r3) : "r"(saddr));
}
__device__ __forceinline__ void mma16816(float* c, const uint32_t* a,
                                         uint32_t b0, uint32_t b1) {
    asm volatile("mma.sync.aligned.m16n8k16.row.col.f32.f16.f16.f32 "
                 "{%0,%1,%2,%3}, {%4,%5,%6,%7}, {%8,%9}, {%0,%1,%2,%3};"
                 : "+f"(c[0]), "+f"(c[1]), "+f"(c[2]), "+f"(c[3])
                 : "r"(a[0]), "r"(a[1]), "r"(a[2]), "r"(a[3]), "r"(b0), "r"(b1));
}

// ---------------------------------------------------------------------------
// fused X precompute (both dirs via blockIdx.z), tile 64x128
// ---------------------------------------------------------------------------
__global__ __launch_bounds__(256)
void xgemm_kernel(const float* __restrict__ emb, const int* __restrict__ xidx,
                  const float* __restrict__ Wf, const float* __restrict__ Wb,
                  const float* __restrict__ b1f, const float* __restrict__ b2f,
                  const float* __restrict__ b1b, const float* __restrict__ b2b,
                  float* __restrict__ Cf, float* __restrict__ Cb)
{
    const int z = blockIdx.z;
    const float* Bm    = z ? Wb  : Wf;
    const float* bias1 = z ? b1b : b1f;
    const float* bias2 = z ? b2b : b2f;
    float*       C     = z ? Cb  : Cf;

    __shared__ float As[8][64];
    __shared__ float Bs[8][128];

    int tid = threadIdx.x;
    int tx = tid & 15, ty = tid >> 4;
    int m0 = blockIdx.y * 64, n0 = blockIdx.x * 128;

    ull acc[4][4];
#pragma unroll
    for (int i = 0; i < 4; i++)
#pragma unroll
        for (int j = 0; j < 4; j++) acc[i][j] = 0ull;

    for (int k0 = 0; k0 < 512; k0 += 8) {
        {
            int kk = tid & 7, row = tid >> 3;
            As[kk][row] = emb[(size_t)xidx[m0 + row] * 512 + k0 + kk];
            int e2 = 256 + tid;
            int kk2 = e2 & 7, row2 = e2 >> 3;
            As[kk2][row2] = emb[(size_t)xidx[m0 + row2] * 512 + k0 + kk2];
        }
#pragma unroll
        for (int r = 0; r < 4; r++) {
            int e = r * 256 + tid;
            int kk = e & 7, row = e >> 3;
            Bs[kk][row] = Bm[(size_t)(n0 + row) * 512 + k0 + kk];
        }
        __syncthreads();
#pragma unroll
        for (int kk = 0; kk < 8; kk++) {
            float4 a = *(const float4*)&As[kk][ty * 4];
            ulonglong2 b0 = *(const ulonglong2*)&Bs[kk][tx * 8];
            ulonglong2 b1 = *(const ulonglong2*)&Bs[kk][tx * 8 + 4];
            float av[4] = {a.x, a.y, a.z, a.w};
#pragma unroll
            for (int i = 0; i < 4; i++) {
                ull ad = pack2(av[i], av[i]);
                ffma2(acc[i][0], ad, b0.x); ffma2(acc[i][1], ad, b0.y);
                ffma2(acc[i][2], ad, b1.x); ffma2(acc[i][3], ad, b1.y);
            }
        }
        __syncthreads();
    }
#pragma unroll
    for (int i = 0; i < 4; i++) {
        float* crow = C + (size_t)(m0 + ty * 4 + i) * 2048 + n0 + tx * 8;
#pragma unroll
        for (int j2 = 0; j2 < 4; j2++) {
            float2 v = unpk(acc[i][j2]);
            int n = n0 + tx * 8 + j2 * 2;
            crow[j2 * 2]     = v.x + bias1[n] + bias2[n];
            crow[j2 * 2 + 1] = v.y + bias1[n + 1] + bias2[n + 1];
        }
    }
}

// ---------------------------------------------------------------------------
// Whh 3-term split, rows re-ordered unit-major: W3[dir][u*4+g] =
//   [wh | wl*2^11 | wh*2^-6]
// ---------------------------------------------------------------------------
__global__ __launch_bounds__(256)
void whh_split_kernel(const float* __restrict__ Wf, const float* __restrict__ Wb)
{
    int dir = blockIdx.y;
    int no = blockIdx.x;                 // original row g*512+u
    int g = no >> 9, u = no & 511;
    const float* src = (dir ? Wb : Wf) + (size_t)no * 512;
    __half* dst = g_W3[dir][u * 4 + g];
    for (int k = threadIdx.x; k < 512; k += 256) {
        float w = src[k];
        __half wh = __float2half(w);
        float whf = __half2float(wh);
        dst[k]        = wh;
        dst[512 + k]  = __float2half((w - whf) * 2048.0f);
        dst[1024 + k] = __float2half(whf * (1.0f / 64.0f));
    }
}

// ---------------------------------------------------------------------------
// One recurrence step: gates = h3 @ W3^T (HMMA, K=1536) + X, then LSTM cell,
// cumsum, and h3 re-split, all fused. Tile 64 rows x 128 cols (=32 units).
// ---------------------------------------------------------------------------
#define RSTR 40
#define RCHUNK 48                       // 1536/32
#define A_HALVES (64 * RSTR)            // per buffer
#define B_HALVES (128 * RSTR)
#define SM_BYTES 34048                  // >= max(2*(A+B)*2, 64*132*4)

__global__ __launch_bounds__(256, 2)
void lstm_step_kernel(const float* __restrict__ Xf, const float* __restrict__ Xb,
                      int s)
{
    __shared__ __align__(16) char smbuf[SM_BYTES];
    __shared__ int rowmap[64];          // slot*4 + nw*2 + active

    const int dir = blockIdx.z;
    const int L = s + 1;
    const int Mact = 8 * L;
    const int t = dir ? (31 - s) : s;
    const int m0 = blockIdx.y * 64;
    const int n0 = blockIdx.x * 128;    // over 2048 (unit*4+gate)
    const int u0 = n0 >> 2;
    const int tid = threadIdx.x, wid = tid >> 5, lane = tid & 31;
    const int rb = s & 1, wb = rb ^ 1;

    __half* As = (__half*)smbuf;                    // [2][A_HALVES]
    __half* Bs = (__half*)smbuf + 2 * A_HALVES;     // [2][B_HALVES]
    float* gates = (float*)smbuf;                   // overlay, used post-K-loop

    if (tid < 64) {
        int r = m0 + tid;
        int v = 0;
        if (r < Mact) {
            int bb = r / L, j = r - bb * L;
            int slot = dir ? (bb * 32 + t + j) : (bb * 32 + j);
            int nw = dir ? (j == 0) : (j == s);
            v = slot * 4 + nw * 2 + 1;
        }
        rowmap[tid] = v;
    }
    __syncthreads();

    // staging source pointers
    const int ar = tid >> 2, akseg = (tid & 3) * 8;
    int am = rowmap[ar];
    const __half* asrc = g_h3[dir][rb][(am & 2) || !(am & 1) ? ZROW : (am >> 2)]
                         + akseg;
    const __half* bsrc0 = g_W3[dir][n0 + (tid >> 2)] + akseg;
    const __half* bsrc1 = g_W3[dir][n0 + 64 + (tid >> 2)] + akseg;
    const int a_soff = ar * RSTR + akseg;
    const int b_soff0 = (tid >> 2) * RSTR + akseg;
    const int b_soff1 = (64 + (tid >> 2)) * RSTR + akseg;

    float acc[2][4][4];
#pragma unroll
    for (int i = 0; i < 2; i++)
#pragma unroll
        for (int j = 0; j < 4; j++)
#pragma unroll
            for (int r = 0; r < 4; r++) acc[i][j][r] = 0.f;

    const uint32_t sbase = (uint32_t)__cvta_generic_to_shared(smbuf);
    const int wm = wid & 1, wn = wid >> 1;
    const int a_row = wm * 32 + (lane & 15);
    const int a_col = (lane >> 4) * 8;
    const int b_row = wn * 32 + ((lane >> 4) << 3) + (lane & 7);
    const int b_col = ((lane >> 3) & 1) * 8;

    // prologue: chunk 0
    {
        uint4 av = __ldg((const uint4*)(asrc));
        uint4 bv0 = __ldg((const uint4*)(bsrc0));
        uint4 bv1 = __ldg((const uint4*)(bsrc1));
        *(uint4*)&As[a_soff] = av;
        *(uint4*)&Bs[b_soff0] = bv0;
        *(uint4*)&Bs[b_soff1] = bv1;
    }
    __syncthreads();

    for (int c = 0; c < RCHUNK; c++) {
        const int cur = c & 1;
        uint4 av, bv0, bv1;
        if (c + 1 < RCHUNK) {
            av  = __ldg((const uint4*)(asrc  + (c + 1) * 32));
            bv0 = __ldg((const uint4*)(bsrc0 + (c + 1) * 32));
            bv1 = __ldg((const uint4*)(bsrc1 + (c + 1) * 32));
        }
        uint32_t abuf = sbase + cur * A_HALVES * 2;
        uint32_t bbuf = sbase + (2 * A_HALVES + cur * B_HALVES) * 2;
#pragma unroll
        for (int kb = 0; kb < 32; kb += 16) {
            uint32_t a[2][4], b[2][4];
#pragma unroll
            for (int i = 0; i < 2; i++)
                ldsm4(a[i][0], a[i][1], a[i][2], a[i][3],
                      abuf + ((a_row + i * 16) * RSTR + kb + a_col) * 2);
#pragma unroll
            for (int j = 0; j < 2; j++)
                ldsm4(b[j][0], b[j][1], b[j][2], b[j][3],
                      bbuf + ((b_row + j * 16) * RSTR + kb + b_col) * 2);
#pragma unroll
            for (int i = 0; i < 2; i++)
#pragma unroll
                for (int j = 0; j < 2; j++) {
                    mma16816(acc[i][j * 2],     a[i], b[j][0], b[j][1]);
                    mma16816(acc[i][j * 2 + 1], a[i], b[j][2], b[j][3]);
                }
        }
        __syncthreads();
        if (c + 1 < RCHUNK) {
            const int nxt = cur ^ 1;
            *(uint4*)&As[nxt * A_HALVES + a_soff] = av;
            *(uint4*)&Bs[nxt * B_HALVES + b_soff0] = bv0;
            *(uint4*)&Bs[nxt * B_HALVES + b_soff1] = bv1;
            __syncthreads();
        }
    }

    // acc -> gates smem (overlay on staging; all ldsm done)
#pragma unroll
    for (int i = 0; i < 2; i++) {
        int row = wm * 32 + i * 16 + (lane >> 2);
#pragma unroll
        for (int jj = 0; jj < 4; jj++) {
            int col = wn * 32 + jj * 8 + (lane & 3) * 2;
            gates[row * 132 + col]           = acc[i][jj][0];
            gates[row * 132 + col + 1]       = acc[i][jj][1];
            gates[(row + 8) * 132 + col]     = acc[i][jj][2];
            gates[(row + 8) * 132 + col + 1] = acc[i][jj][3];
        }
    }
    __syncthreads();

    // LSTM cell: lane -> unit, warp -> 8 rows
    const float* Xd = dir ? Xb : Xf;
    float* Cst = dir ? g_Cb : g_Cf;
    float* Ad  = dir ? g_Ab : g_Af;
    const int u = lane, ug = u0 + u;
    const int tprev = dir ? (t + 1) : (t - 1);
#pragma unroll
    for (int rr = 0; rr < 8; rr++) {
        int r = wid * 8 + rr;
        int meta = rowmap[r];
        if (!(meta & 1)) continue;
        int slot = meta >> 2;
        bool nw = meta & 2;
        int bb = slot >> 5;
        float4 gv = *(const float4*)&gates[r * 132 + 4 * u];
        const float* Xrow = Xd + (size_t)(bb * 32 + t) * 2048;
        float gi = gv.x + Xrow[ug];
        float gf = gv.y + Xrow[512 + ug];
        float gg = gv.z + Xrow[1024 + ug];
        float go = gv.w + Xrow[1536 + ug];
        float cprev = nw ? 0.f : __ldcg(&Cst[slot * 512 + ug]);
        float ig = 1.f / (1.f + __expf(-gi));
        float fg = 1.f / (1.f + __expf(-gf));
        float og = 1.f / (1.f + __expf(-go));
        float gt = tanhf(gg);
        float cc = fg * cprev + ig * gt;
        float hh = og * tanhf(cc);
        Cst[slot * 512 + ug] = cc;
        float ap = nw ? 0.f : __ldcg(&Ad[((size_t)slot * 32 + tprev) * 512 + ug]);
        Ad[((size_t)slot * 32 + t) * 512 + ug] = ap + hh;
        __half hh16 = __float2half(hh);
        float hlf = hh - __half2float(hh16);
        __half* hrow = g_h3[dir][wb][slot];
        hrow[ug]        = hh16;
        hrow[512 + ug]  = __float2half(__half2float(hh16) * (1.0f / 2048.0f));
        hrow[1024 + ug] = __float2half(hlf * 64.0f);
    }
}

// ---------------------------------------------------------------------------
// span means -> fp16 2-term split:  A2 = [Mh | Mh*2^-11]
// ---------------------------------------------------------------------------
__global__ __launch_bounds__(256)
void mean_split_kernel()
{
    int sidx = blockIdx.x;
    int b = blockIdx.y;
    int k = 1, off = 0;
    while (off + (32 - k) <= sidx) { off += (32 - k); k++; }
    int p = sidx - off;
    int q = p + k;
    float inv = 1.f / (float)(k + 1);

    int tid = threadIdx.x;
    __half* dst = g_Acat + (size_t)(b * 496 + sidx) * KC2;
    const float* af = g_Af + (((size_t)(b * 32 + p)) * 32 + q) * 512;
    const float* ab = g_Ab + (((size_t)(b * 32 + q)) * 32 + p) * 512;
    const float s11 = 1.0f / 2048.0f;
    for (int uu = tid; uu < 512; uu += 256) {
        float f1 = af[uu] * inv;
        __half h1 = __float2half(f1);
        dst[uu]        = h1;
        dst[1024 + uu] = __float2half(__half2float(h1) * s11);
        float f2 = ab[uu] * inv;
        __half h2 = __float2half(f2);
        dst[512 + uu]  = h2;
        dst[1536 + uu] = __float2half(__half2float(h2) * s11);
    }
}

// ---------------------------------------------------------------------------
// Wout fp16 2-term split:  B2 = [Wh | (W - Wh)*2^11]
// ---------------------------------------------------------------------------
__global__ __launch_bounds__(256)
void wout_split_kernel(const float* __restrict__ Wout)
{
    int n = blockIdx.x;
    __half* dst = g_Bcat + (size_t)n * KC2;
    const float* src = Wout + (size_t)n * 1024;
    for (int k = threadIdx.x; k < 1024; k += 256) {
        float w = src[k];
        __half h = __float2half(w);
        dst[k]        = h;
        dst[1024 + k] = __float2half((w - __half2float(h)) * 2048.0f);
    }
}

// ---------------------------------------------------------------------------
// Projection via mma.sync (fp16, fp32 accum): out = A2 @ B2^T + bout
// ---------------------------------------------------------------------------
#define PSTRIDE 40
#define PCHUNK  32
#define NCHUNK  (KC2 / PCHUNK)   // 64

__global__ __launch_bounds__(256, 2)
void proj_mma_kernel(const float* __restrict__ bout, float* __restrict__ out)
{
    __shared__ __half As[2][128 * PSTRIDE];
    __shared__ __half Bs[2][128 * PSTRIDE];

    const int tid = threadIdx.x;
    const int wid = tid >> 5;
    const int lane = tid & 31;
    const int wm = wid & 1;
    const int wn = wid >> 1;
    const int m0 = blockIdx.y * 128;
    const int n0 = blockIdx.x * 128;

    const __half* Ag = g_Acat + (size_t)m0 * KC2;
    const __half* Bg = g_Bcat + (size_t)n0 * KC2;

    const int srow = tid >> 1;
    const int scol = (tid & 1) * 16;
    const __half* agp = Ag + (size_t)srow * KC2 + scol;
    const __half* bgp = Bg + (size_t)srow * KC2 + scol;
    const int ssoff = srow * PSTRIDE + scol;

    float acc[4][4][4];
#pragma unroll
    for (int i = 0; i < 4; i++)
#pragma unroll
        for (int j = 0; j < 4; j++)
#pragma unroll
            for (int r = 0; r < 4; r++) acc[i][j][r] = 0.f;

    uint32_t a_base = (uint32_t)__cvta_generic_to_shared(&As[0][0]);
    uint32_t b_base = (uint32_t)__cvta_generic_to_shared(&Bs[0][0]);
    const uint32_t bufA = 128 * PSTRIDE * 2;
    const int a_row = wm * 64 + (lane & 15);
    const int a_col = (lane >> 4) * 8;
    const int b_row = wn * 32 + ((lane >> 4) << 3) + (lane & 7);
    const int b_col = ((lane >> 3) & 1) * 8;

    {
        uint4 av0 = __ldg((const uint4*)(agp));
        uint4 av1 = __ldg((const uint4*)(agp + 8));
        uint4 bv0 = __ldg((const uint4*)(bgp));
        uint4 bv1 = __ldg((const uint4*)(bgp + 8));
        *(uint4*)&As[0][ssoff]     = av0;
        *(uint4*)&As[0][ssoff + 8] = av1;
        *(uint4*)&Bs[0][ssoff]     = bv0;
        *(uint4*)&Bs[0][ssoff + 8] = bv1;
    }
    __syncthreads();

    for (int c = 0; c < NCHUNK; c++) {
        const int cur = c & 1;
        uint4 av0, av1, bv0, bv1;
        if (c + 1 < NCHUNK) {
            const __half* ag = agp + (c + 1) * PCHUNK;
            const __half* bg = bgp + (c + 1) * PCHUNK;
            av0 = __ldg((const uint4*)(ag));
            av1 = __ldg((const uint4*)(ag + 8));
            bv0 = __ldg((const uint4*)(bg));
            bv1 = __ldg((const uint4*)(bg + 8));
        }

        uint32_t abuf = a_base + cur * bufA;
        uint32_t bbuf = b_base + cur * bufA;
#pragma unroll
        for (int kb = 0; kb < PCHUNK; kb += 16) {
            uint32_t a[4][4];
            uint32_t b[2][4];
#pragma unroll
            for (int i = 0; i < 4; i++)
                ldsm4(a[i][0], a[i][1], a[i][2], a[i][3],
                      abuf + ((a_row + i * 16) * PSTRIDE + kb + a_col) * 2);
#pragma unroll
            for (int j = 0; j < 2; j++)
                ldsm4(b[j][0], b[j][1], b[j][2], b[j][3],
                      bbuf + ((b_row + j * 16) * PSTRIDE + kb + b_col) * 2);
#pragma unroll
            for (int i = 0; i < 4; i++) {
#pragma unroll
                for (int j = 0; j < 2; j++) {
                    mma16816(acc[i][j * 2],     a[i], b[j][0], b[j][1]);
                    mma16816(acc[i][j * 2 + 1], a[i], b[j][2], b[j][3]);
                }
            }
        }
        __syncthreads();
        if (c + 1 < NCHUNK) {
            const int nxt = cur ^ 1;
            *(uint4*)&As[nxt][ssoff]     = av0;
            *(uint4*)&As[nxt][ssoff + 8] = av1;
            *(uint4*)&Bs[nxt][ssoff]     = bv0;
            *(uint4*)&Bs[nxt][ssoff + 8] = bv1;
            __syncthreads();
        }
    }

#pragma unroll
    for (int i = 0; i < 4; i++) {
        int row = m0 + wm * 64 + i * 16 + (lane >> 2);
#pragma unroll
        for (int jj = 0; jj < 4; jj++) {
            int col = n0 + wn * 32 + jj * 8 + (lane & 3) * 2;
            float2 bo = *(const float2*)&bout[col];
            float2 v0 = make_float2(acc[i][jj][0] + bo.x, acc[i][jj][1] + bo.y);
            float2 v1 = make_float2(acc[i][jj][2] + bo.x, acc[i][jj][3] + bo.y);
            *(float2*)&out[(size_t)row * NOUT + col] = v0;
            *(float2*)&out[(size_t)(row + 8) * NOUT + col] = v1;
        }
    }
}

// ---------------------------------------------------------------------------
extern "C" void kernel_launch(void* const* d_in, const int* in_sizes, int n_in,
                              void* d_out, int out_size)
{
    const int*   x     = (const int*)  d_in[0];
    const float* emb   = (const float*)d_in[2];
    const float* Wih_f = (const float*)d_in[3];
    const float* Whh_f = (const float*)d_in[4];
    const float* bih_f = (const float*)d_in[5];
    const float* bhh_f = (const float*)d_in[6];
    const float* Wih_b = (const float*)d_in[7];
    const float* Whh_b = (const float*)d_in[8];
    const float* bih_b = (const float*)d_in[9];
    const float* bhh_b = (const float*)d_in[10];
    const float* Wout  = (const float*)d_in[11];
    const float* bout  = (const float*)d_in[12];
    float* out = (float*)d_out;

    float *Xf_p, *Xb_p;
    cudaGetSymbolAddress((void**)&Xf_p, g_Xf);
    cudaGetSymbolAddress((void**)&Xb_p, g_Xb);

    dim3 blk(256);

    wout_split_kernel<<<NOUT, blk>>>(Wout);
    whh_split_kernel<<<dim3(2048, 2), blk>>>(Whh_f, Whh_b);

    xgemm_kernel<<<dim3(16, 4, 2), blk>>>(emb, x, Wih_f, Wih_b,
                                          bih_f, bhh_f, bih_b, bhh_b,
                                          Xf_p, Xb_p);

    for (int s = 0; s < 32; s++) {
        dim3 grid(16, (8 * (s + 1) + 63) / 64, 2);
        lstm_step_kernel<<<grid, blk>>>(Xf_p, Xb_p, s);
    }

    mean_split_kernel<<<dim3(496, 8), blk>>>();

    proj_mma_kernel<<<dim3(60, 31), blk>>>(bout, out);
}